// round 13
// baseline (speedup 1.0000x reference)
#include <cuda_runtime.h>
#include <cuda_bf16.h>
#include <math.h>
#include <stdint.h>
#include <string.h>

#define BB 8
#define CC 512
#define TT 8
#define WW 28
#define HWs 784
#define THW 6272
#define RR 64
#define KK 4
#define CQ 128
#define PP 512
#define EPSC 1e-5f

// ---------------- device scratch (no allocations allowed) ----------------
__device__ __align__(256) int   g_spt[BB*RR];
__device__ __align__(256) float g_tp[BB*RR*HWs];
__device__ __align__(256) float g_aff[BB*RR*THW];
__device__ __align__(256) int   g_topk[BB*RR*TT*KK];
__device__ __align__(256) float g_traj[BB*KK*CC*TT*RR];      // (B,K,C,T,R)
__device__ __align__(256) float g_fusek[BB*KK*CQ*TT*RR];     // (B,K,Cq,T,R)
__device__ __align__(256) float g_fuse[BB*CQ*TT*RR];         // (B,Cq,T,R)
__device__ __align__(256) float g_proj[(size_t)BB*THW*PP];   // (B,S,P) logits (transposed)
__device__ __align__(256) float g_sinv[BB*THW];

// bf16 split operands (row-major [row][K])
__device__ __align__(256) __nv_bfloat16 g_trAh[BB*RR*CC];    // tresT [r][c]
__device__ __align__(256) __nv_bfloat16 g_trAl[BB*RR*CC];
__device__ __align__(256) __nv_bfloat16 g_A1h[BB*PP*CC];     // pointsT [p][c]
__device__ __align__(256) __nv_bfloat16 g_A1l[BB*PP*CC];
__device__ __align__(256) __nv_bfloat16 g_B1h[(size_t)BB*THW*CC]; // xT [s][c]
__device__ __align__(256) __nv_bfloat16 g_B1l[(size_t)BB*THW*CC];
__device__ __align__(256) __nv_bfloat16 g_A2h[BB*CC*PP];     // tc [c][p]
__device__ __align__(256) __nv_bfloat16 g_A2l[BB*CC*PP];
__device__ __align__(256) __nv_bfloat16 g_B2h[(size_t)BB*THW*PP]; // expT [s][p] (single)

// ================= sm_80-class PTX helpers ==================================
__device__ __forceinline__ uint32_t smem_u32(const void* p){
    uint32_t a;
    asm("{ .reg .u64 t; cvta.to.shared.u64 t, %1; cvt.u32.u64 %0, t; }" : "=r"(a) : "l"(p));
    return a;
}
__device__ __forceinline__ void ldmx4(uint32_t* r, uint32_t addr){
    asm volatile("ldmatrix.sync.aligned.m8n8.x4.shared.b16 {%0,%1,%2,%3}, [%4];"
                 : "=r"(r[0]), "=r"(r[1]), "=r"(r[2]), "=r"(r[3]) : "r"(addr));
}
__device__ __forceinline__ void mma16816(float* c, const uint32_t* a, uint32_t b0, uint32_t b1){
    asm volatile("mma.sync.aligned.m16n8k16.row.col.f32.bf16.bf16.f32 "
                 "{%0,%1,%2,%3}, {%4,%5,%6,%7}, {%8,%9}, {%0,%1,%2,%3};"
                 : "+f"(c[0]), "+f"(c[1]), "+f"(c[2]), "+f"(c[3])
                 : "r"(a[0]), "r"(a[1]), "r"(a[2]), "r"(a[3]), "r"(b0), "r"(b1));
}
__device__ __forceinline__ void cpa16(uint32_t s, const void* g){
    asm volatile("cp.async.cg.shared.global [%0], [%1], 16;" :: "r"(s), "l"(g));
}
#define CP_COMMIT() asm volatile("cp.async.commit_group;" ::: "memory")
#define CP_WAIT(N)  asm volatile("cp.async.wait_group %0;" :: "n"(N) : "memory")

__device__ __forceinline__ uint32_t pack_bf16(__nv_bfloat16 lo, __nv_bfloat16 hi){
    uint16_t ul, uh;
    memcpy(&ul, &lo, 2); memcpy(&uh, &hi, 2);
    return (uint32_t)ul | ((uint32_t)uh << 16);
}
__device__ __forceinline__ void split_bf(float v, __nv_bfloat16& h, __nv_bfloat16& l){
    h = __float2bfloat16(v);
    l = __float2bfloat16(v - __bfloat162float(h));
}

// ---------------- 1a: g_tp[b][r][s] = (w_reduce @ x[:,:,0,:])[r][s]
__global__ void __launch_bounds__(256) k_tp(const float* __restrict__ x,
                                            const float* __restrict__ wr)
{
    int b = blockIdx.y;
    int s0 = blockIdx.x * 112;
    __shared__ float ws[32][65];
    __shared__ float xs[32][113];
    int tid = threadIdx.x;
    int tx = tid & 15, ty = tid >> 4;
    float acc[4][7];
    #pragma unroll
    for (int i=0;i<4;i++)
        #pragma unroll
        for (int j=0;j<7;j++) acc[i][j]=0.f;

    for (int cc = 0; cc < CC; cc += 32){
        #pragma unroll
        for (int it=0; it<8; it++){
            int id = tid + it*256;
            int r = id >> 5, k = id & 31;
            ws[k][r] = wr[r*CC + cc + k];
        }
        #pragma unroll
        for (int it=0; it<14; it++){
            int id = tid + it*256;
            int k = id / 112, s = id % 112;
            xs[k][s] = x[(size_t)(b*CC + cc + k)*THW + s0 + s];
        }
        __syncthreads();
        #pragma unroll 4
        for (int k=0;k<32;k++){
            float a[4], bv[7];
            #pragma unroll
            for (int i=0;i<4;i++) a[i] = ws[k][ty*4+i];
            #pragma unroll
            for (int j=0;j<7;j++) bv[j] = xs[k][tx*7+j];
            #pragma unroll
            for (int i=0;i<4;i++)
                #pragma unroll
                for (int j=0;j<7;j++) acc[i][j] += a[i]*bv[j];
        }
        __syncthreads();
    }
    #pragma unroll
    for (int i=0;i<4;i++)
        #pragma unroll
        for (int j=0;j<7;j++)
            g_tp[(b*RR + ty*4+i)*HWs + s0 + tx*7 + j] = acc[i][j];
}

// ---------------- 1b: argmax over HW of bn1(g_tp)
__global__ void k_tp_argmax(const float* __restrict__ g1, const float* __restrict__ b1,
                            const float* __restrict__ m1, const float* __restrict__ v1)
{
    int w = blockIdx.x*4 + (threadIdx.x >> 5);
    int lane = threadIdx.x & 31;
    int r = w & 63;
    float scale = g1[r] * rsqrtf(v1[r] + EPSC);
    float shift = b1[r] - m1[r]*scale;
    const float* row = g_tp + (size_t)w*HWs;
    float best = -3.4e38f; int bi = 0;
    #pragma unroll
    for (int i=0;i<25;i++){
        int idx = i*32 + lane;
        if (idx < HWs){
            float v = row[idx]*scale + shift;
            if (v > best){ best = v; bi = idx; }
        }
    }
    #pragma unroll
    for (int off=16; off; off>>=1){
        float ov = __shfl_down_sync(0xffffffffu, best, off);
        int oi = __shfl_down_sync(0xffffffffu, bi, off);
        if (ov > best || (ov == best && oi < bi)){ best = ov; bi = oi; }
    }
    if (lane == 0) g_spt[w] = bi;
}

// ---------------- 2: template_resample gather -> bf16 split [b][r][c]
__global__ void k_tresT(const float* __restrict__ x){
    int o = blockIdx.x*256 + threadIdx.x;
    int c = o & 511; int r = (o>>9) & 63; int b = o >> 15;
    int idx = g_spt[b*RR + r];
    float v = x[(size_t)(b*CC + c)*THW + idx];
    __nv_bfloat16 h, l; split_bf(v, h, l);
    g_trAh[o] = h; g_trAl[o] = l;
}

// ================= HMMA affinity: M=64, N=6272, K=512, 3-pass bf16 =========
#define ROWB   80
#define AF_STAGE (384*ROWB)       // 30720
#define AFF_SMEM (2*AF_STAGE)     // 61440

__global__ void __launch_bounds__(128, 3) k_affinity(){
    extern __shared__ char smem[];
    const uint32_t sb0 = smem_u32(smem);
    const int tid = threadIdx.x;
    const int wid = tid >> 5, lane = tid & 31;

    const int n0 = blockIdx.x * 128;
    const int b  = blockIdx.y;

    const __nv_bfloat16* Ah = g_trAh + (size_t)b*RR*512;
    const __nv_bfloat16* Al = g_trAl + (size_t)b*RR*512;
    const __nv_bfloat16* Bh = g_B1h + ((size_t)b*THW + n0)*512;
    const __nv_bfloat16* Bl = g_B1l + ((size_t)b*THW + n0)*512;

    float acc[4][4][4];
    #pragma unroll
    for (int i=0;i<4;i++)
        #pragma unroll
        for (int j=0;j<4;j++)
            #pragma unroll
            for (int q=0;q<4;q++) acc[i][j][q]=0.f;

    const int lrow = (lane & 7) + ((lane >> 3) & 1) * 8;
    const int lcol = (lane >> 4) * 16;

    auto load_chunk = [&](int i, int buf){
        uint32_t sbase = sb0 + buf*AF_STAGE;
        #pragma unroll
        for (int it=0; it<12; it++){
            int id = tid + it*128;           // 0..1535
            int row = id >> 2, c = id & 3;
            const __nv_bfloat16* g;
            if (row < 128) g = (row < 64 ? Ah : Al) + (size_t)(row & 63)*512;
            else           g = (row < 256 ? Bh : Bl) + (size_t)((row - 128) & 127)*512;
            cpa16(sbase + row*ROWB + c*16, g + i*32 + c*8);
        }
        CP_COMMIT();
    };

    load_chunk(0, 0);

    for (int i = 0; i < 16; i++){
        if (i < 15){ load_chunk(i+1, (i+1)&1); CP_WAIT(1); }
        else       { CP_WAIT(0); }
        __syncthreads();

        const uint32_t sbuf = sb0 + (i&1)*AF_STAGE;
        #pragma unroll
        for (int kt=0; kt<2; kt++){
            const uint32_t koff = kt*32 + lcol;
            uint32_t a[4][4], bh[2][4], bl[2][4];
            // load Ah + Bh
            #pragma unroll
            for (int mt=0; mt<4; mt++)
                ldmx4(a[mt], sbuf + (uint32_t)(mt*16 + lrow)*ROWB + koff);
            #pragma unroll
            for (int np=0; np<2; np++)
                ldmx4(bh[np], sbuf + 128*ROWB + (uint32_t)(wid*32 + np*16 + lrow)*ROWB + koff);
            #pragma unroll
            for (int mt=0; mt<4; mt++)
                #pragma unroll
                for (int nt=0; nt<4; nt++)
                    mma16816(acc[mt][nt], a[mt],
                             (nt&1)?bh[nt>>1][1]:bh[nt>>1][0],
                             (nt&1)?bh[nt>>1][3]:bh[nt>>1][2]);
            // load Bl, reuse Ah
            #pragma unroll
            for (int np=0; np<2; np++)
                ldmx4(bl[np], sbuf + 256*ROWB + (uint32_t)(wid*32 + np*16 + lrow)*ROWB + koff);
            #pragma unroll
            for (int mt=0; mt<4; mt++)
                #pragma unroll
                for (int nt=0; nt<4; nt++)
                    mma16816(acc[mt][nt], a[mt],
                             (nt&1)?bl[nt>>1][1]:bl[nt>>1][0],
                             (nt&1)?bl[nt>>1][3]:bl[nt>>1][2]);
            // load Al, reuse Bh
            #pragma unroll
            for (int mt=0; mt<4; mt++)
                ldmx4(a[mt], sbuf + 64*ROWB + (uint32_t)(mt*16 + lrow)*ROWB + koff);
            #pragma unroll
            for (int mt=0; mt<4; mt++)
                #pragma unroll
                for (int nt=0; nt<4; nt++)
                    mma16816(acc[mt][nt], a[mt],
                             (nt&1)?bh[nt>>1][1]:bh[nt>>1][0],
                             (nt&1)?bh[nt>>1][3]:bh[nt>>1][2]);
        }
        __syncthreads();
    }

    const int g = lane >> 2, t = lane & 3;
    float* OutB = g_aff + (size_t)b*RR*THW;
    #pragma unroll
    for (int mt=0; mt<4; mt++){
        #pragma unroll
        for (int nt=0; nt<4; nt++){
            int row0 = mt*16 + g;
            int col  = n0 + wid*32 + nt*8 + t*2;
            size_t o0 = (size_t)row0*THW + col;
            size_t o1 = o0 + (size_t)8*THW;
            *(float2*)&OutB[o0] = make_float2(acc[mt][nt][0], acc[mt][nt][1]);
            *(float2*)&OutB[o1] = make_float2(acc[mt][nt][2], acc[mt][nt][3]);
        }
    }
}

// ---------------- 4: top-4 over HW per (b,r,t)
__global__ void k_topk(){
    int w = blockIdx.x*4 + (threadIdx.x >> 5);
    int lane = threadIdx.x & 31;
    const float* row = g_aff + (size_t)(w >> 3)*THW + (w & 7)*HWs;
    float lv[25];
    #pragma unroll
    for (int i=0;i<25;i++){
        int idx = i*32 + lane;
        lv[i] = (idx < HWs) ? row[idx] : -3.4e38f;
    }
    for (int kq=0;kq<KK;kq++){
        float v = -3.4e38f; int pos = 0;
        #pragma unroll
        for (int i=0;i<25;i++) if (lv[i] > v){ v = lv[i]; pos = i; }
        int gi = pos*32 + lane;
        #pragma unroll
        for (int off=16; off; off>>=1){
            float ov = __shfl_down_sync(0xffffffffu, v, off);
            int oi = __shfl_down_sync(0xffffffffu, gi, off);
            if (ov > v || (ov == v && oi < gi)){ v = ov; gi = oi; }
        }
        gi = __shfl_sync(0xffffffffu, gi, 0);
        #pragma unroll
        for (int i=0;i<25;i++) if (i*32 + lane == gi) lv[i] = -3.4e38f;
        if (lane == 0) g_topk[w*KK + kq] = gi;
    }
}

// ---------------- 5: trajectory gather
__global__ void k_traj(const float* __restrict__ x){
    int o = blockIdx.x*256 + threadIdx.x;
    int r = o & 63, t = (o>>6)&7, c = (o>>9)&511, kq = (o>>18)&3, b = o>>20;
    int idx = g_topk[((b*RR + r)*TT + t)*KK + kq];
    g_traj[o] = x[((size_t)(b*CC + c)*TT + t)*HWs + idx];
}

// ---------------- 6: per-k projection
__global__ void __launch_bounds__(256) k_fusek(
    const float* __restrict__ wp,
    const float* __restrict__ g2, const float* __restrict__ b2,
    const float* __restrict__ m2, const float* __restrict__ v2)
{
    int blk = blockIdx.x;
    int b = blk >> 5, ks = (blk >> 3) & 3, t = blk & 7;
    int tid = threadIdx.x, tx = tid & 15, ty = tid >> 4;
    __shared__ float As[32][132];
    __shared__ float Bs[32][64];
    float acc[8][4];
    #pragma unroll
    for (int i=0;i<8;i++){
        #pragma unroll
        for (int j=0;j<4;j++) acc[i][j]=0.f;
    }
    const float* Tb = g_traj + (size_t)(b*KK + ks)*CC*(TT*RR) + t*RR;
    for (int cc = 0; cc < CC; cc += 32){
        #pragma unroll
        for (int i=0;i<16;i++){
            int l = tid + 256*i;
            int k = l & 31, m = l >> 5;
            As[k][m] = wp[m*514 + cc + k];
        }
        #pragma unroll
        for (int i=0;i<8;i++){
            int l = tid + 256*i;
            int n = l & 63, k = l >> 6;
            Bs[k][n] = Tb[(size_t)(cc + k)*(TT*RR) + n];
        }
        __syncthreads();
        #pragma unroll
        for (int k=0;k<32;k++){
            float4 a0 = *(const float4*)&As[k][ty*4];
            float4 a1 = *(const float4*)&As[k][64 + ty*4];
            float4 bv = *(const float4*)&Bs[k][tx*4];
            float av[8] = {a0.x,a0.y,a0.z,a0.w,a1.x,a1.y,a1.z,a1.w};
            float bw[4] = {bv.x,bv.y,bv.z,bv.w};
            #pragma unroll
            for (int i=0;i<8;i++){
                #pragma unroll
                for (int j=0;j<4;j++) acc[i][j] += av[i]*bw[j];
            }
        }
        __syncthreads();
    }
    #pragma unroll
    for (int j=0;j<4;j++){
        int r = tx*4 + j;
        int idx = g_topk[((b*RR + r)*TT + t)*KK + ks];
        float rv = (float)(idx / WW) * (1.f/28.f);
        float cv = (float)(idx % WW) * (1.f/28.f);
        #pragma unroll
        for (int i=0;i<8;i++){
            int q = (i<4) ? ty*4+i : 64 + ty*4 + i - 4;
            acc[i][j] += wp[q*514 + 512]*rv + wp[q*514 + 513]*cv;
        }
    }
    #pragma unroll
    for (int i=0;i<8;i++){
        int q = (i<4) ? ty*4+i : 64 + ty*4 + i - 4;
        float sc = g2[q]*rsqrtf(v2[q]+EPSC);
        float sh = b2[q] - m2[q]*sc;
        #pragma unroll
        for (int j=0;j<4;j++){
            int r = tx*4+j;
            g_fusek[((size_t)(b*KK+ks)*CQ + q)*(TT*RR) + t*RR + r] = acc[i][j]*sc + sh;
        }
    }
}

// ---------------- 7: max over k
__global__ void k_maxk(){
    int o = blockIdx.x*256 + threadIdx.x;
    int b = o >> 16, rem = o & 65535;
    float m = g_fusek[(size_t)(b*KK)*65536 + rem];
    #pragma unroll
    for (int ks=1; ks<KK; ks++)
        m = fmaxf(m, g_fusek[(size_t)(b*KK+ks)*65536 + rem]);
    g_fuse[o] = m;
}

// ---------------- 8: temporal conv + bn3 + relu -> A2 bf16 split
__global__ void __launch_bounds__(256) k_tconv(
    const float* __restrict__ wt,
    const float* __restrict__ g3, const float* __restrict__ b3,
    const float* __restrict__ m3, const float* __restrict__ v3)
{
    int b = blockIdx.x >> 3, t = blockIdx.x & 7;
    int coBase = blockIdx.y * 16;
    int r = threadIdx.x & 63;
    int g = threadIdx.x >> 6;
    float acc[4] = {0.f,0.f,0.f,0.f};
    const float* fbase = g_fuse + (size_t)b*CQ*(TT*RR);
    for (int ci=0; ci<CQ; ci++){
        #pragma unroll
        for (int j=0;j<3;j++){
            int tt = t + j - 1;
            if (tt < 0 || tt >= TT) continue;
            float f = fbase[ci*(TT*RR) + tt*RR + r];
            #pragma unroll
            for (int cc=0; cc<4; cc++){
                int co = coBase + g*4 + cc;
                acc[cc] += wt[(co*CQ + ci)*3 + j] * f;
            }
        }
    }
    #pragma unroll
    for (int cc=0; cc<4; cc++){
        int co = coBase + g*4 + cc;
        float sc = g3[co]*rsqrtf(v3[co]+EPSC);
        float sh = b3[co] - m3[co]*sc;
        float v = fmaxf(acc[cc]*sc + sh, 0.f);
        size_t o = (size_t)(b*CC + co)*(TT*RR) + t*RR + r;
        __nv_bfloat16 h, l; split_bf(v, h, l);
        g_A2h[o] = h; g_A2l[o] = l;
    }
}

// ---------------- 9: points (mean over k of traj) transposed + bf16 split
__global__ void __launch_bounds__(256) k_pointsT(){
    __shared__ float s[32][33];
    int ct = blockIdx.x, pt = blockIdx.y, b = blockIdx.z;
    int t = threadIdx.x;
    int rr = t >> 5, cl = t & 31;
    #pragma unroll
    for (int it=0; it<4; it++){
        int c = ct*32 + it*8 + rr;
        size_t base = ((size_t)c << 9) + pt*32 + cl;
        float sm = 0.f;
        #pragma unroll
        for (int k=0;k<KK;k++) sm += g_traj[(((size_t)(b*KK+k))<<18) + base];
        s[it*8+rr][cl] = sm * 0.25f;
    }
    __syncthreads();
    #pragma unroll
    for (int it=0; it<4; it++){
        int pl = it*8 + rr;
        float v = s[cl][pl];
        size_t o = ((size_t)(b*PP) + pt*32 + pl)*CC + ct*32 + cl;
        __nv_bfloat16 h, l; split_bf(v, h, l);
        g_A1h[o] = h; g_A1l[o] = l;
    }
}

// ---------------- 10: x transpose + split: B1[b][s][c] = x[b][c][s]
__global__ void __launch_bounds__(256) k_xT(const float* __restrict__ x){
    __shared__ float s[32][33];
    int ct = blockIdx.x, st = blockIdx.y, b = blockIdx.z;
    int t = threadIdx.x;
    int rr = t >> 5, cl = t & 31;
    #pragma unroll
    for (int it=0; it<4; it++){
        int c = ct*32 + it*8 + rr;
        s[it*8+rr][cl] = x[((size_t)(b*CC) + c)*THW + st*32 + cl];
    }
    __syncthreads();
    #pragma unroll
    for (int it=0; it<2; it++){
        int id = t + it*256;
        int sl = id >> 4;
        int cp = id & 15;
        float v0 = s[cp*2][sl];
        float v1 = s[cp*2+1][sl];
        __nv_bfloat16 h0,l0,h1,l1;
        split_bf(v0, h0, l0); split_bf(v1, h1, l1);
        size_t o = ((size_t)b*THW + st*32 + sl)*CC + ct*32 + cp*2;
        *(uint32_t*)&g_B1h[o] = pack_bf16(h0, h1);
        *(uint32_t*)&g_B1l[o] = pack_bf16(l0, l1);
    }
}

// ---------------- 11: row softmax on projT [s][p] -> B2 bf16 + sinv
__global__ void __launch_bounds__(256) k_soft(){
    int w = blockIdx.x*8 + (threadIdx.x >> 5);     // 0..BB*THW-1
    int lane = threadIdx.x & 31;
    const float* pr = g_proj + (size_t)w*PP;
    float v[16];
    #pragma unroll
    for (int j=0;j<4;j++){
        float4 t = *(const float4*)&pr[j*128 + lane*4];
        v[j*4+0]=t.x; v[j*4+1]=t.y; v[j*4+2]=t.z; v[j*4+3]=t.w;
    }
    float mx = v[0];
    #pragma unroll
    for (int i=1;i<16;i++) mx = fmaxf(mx, v[i]);
    #pragma unroll
    for (int off=16; off; off>>=1) mx = fmaxf(mx, __shfl_xor_sync(0xffffffffu, mx, off));
    float sm = 0.f;
    #pragma unroll
    for (int i=0;i<16;i++){ v[i] = __expf(v[i] - mx); sm += v[i]; }
    #pragma unroll
    for (int off=16; off; off>>=1) sm += __shfl_xor_sync(0xffffffffu, sm, off);
    if (lane == 0) g_sinv[w] = 1.f / sm;

    #pragma unroll
    for (int j=0;j<4;j++){
        __nv_bfloat16 h0 = __float2bfloat16(v[j*4+0]);
        __nv_bfloat16 h1 = __float2bfloat16(v[j*4+1]);
        __nv_bfloat16 h2 = __float2bfloat16(v[j*4+2]);
        __nv_bfloat16 h3 = __float2bfloat16(v[j*4+3]);
        size_t o = (size_t)w*PP + j*128 + lane*4;
        *(uint2*)&g_B2h[o] = make_uint2(pack_bf16(h0, h1), pack_bf16(h2, h3));
    }
}

// ================= HMMA GEMM 128x128, 256 thr ==============================
// MODE 0: projT[s][p] = xT @ pointsT^T   3-pass, 4 tiles (both splits)
// MODE 1: out = x + (tc @ expT^T)*sinv   2-pass, 3 tiles (A split, B single)
#define TILE_SM (128*ROWB)        // 10240
#define GSMEM0 (2*4*TILE_SM)      // 81920
#define GSMEM1 (2*3*TILE_SM)      // 61440

template<int MODE>
__global__ void __launch_bounds__(256, 2)
gemm_bf16(const float* __restrict__ X, float* __restrict__ Out)
{
    constexpr int NT = (MODE==0) ? 4 : 3;
    constexpr int STAGE = NT*TILE_SM;

    extern __shared__ char smem[];
    const uint32_t sb0 = smem_u32(smem);
    const int tid = threadIdx.x;
    const int wid = tid >> 5, lane = tid & 31;
    const int warp_m = wid >> 2, warp_n = wid & 3;

    const int n0 = blockIdx.x * 128;
    const int m0 = blockIdx.y * 128;
    const int b  = blockIdx.z;

    const __nv_bfloat16* tp[NT];
    if (MODE == 0){
        tp[0] = g_B1h + ((size_t)b*THW + m0)*512;
        tp[1] = g_B1l + ((size_t)b*THW + m0)*512;
        tp[2] = g_A1h + ((size_t)(b*512) + n0)*512;
        tp[3] = g_A1l + ((size_t)(b*512) + n0)*512;
    } else {
        tp[0] = g_A2h + ((size_t)(b*512) + m0)*512;
        tp[1] = g_A2l + ((size_t)(b*512) + m0)*512;
        tp[2] = g_B2h + ((size_t)b*THW + n0)*512;
    }

    float acc[4][4][4];
    #pragma unroll
    for (int i=0;i<4;i++)
        #pragma unroll
        for (int j=0;j<4;j++)
            #pragma unroll
            for (int q=0;q<4;q++) acc[i][j][q]=0.f;

    const int lrow = (lane & 7) + ((lane >> 3) & 1) * 8;
    const int lcol = (lane >> 4) * 16;

    auto load_chunk = [&](int i, int buf){
        uint32_t sbase = sb0 + buf*STAGE;
        #pragma unroll
        for (int it=0; it<2*NT; it++){
            int id = tid + it*256;
            int row = id >> 2, c = id & 3;
            int tile = row >> 7, rowin = row & 127;
            const __nv_bfloat16* g = tp[tile] + (size_t)rowin*512 + i*32 + c*8;
            cpa16(sbase + tile*TILE_SM + rowin*ROWB + c*16, g);
        }
        CP_COMMIT();
    };

    load_chunk(0, 0);

    for (int i = 0; i < 16; i++){
        if (i < 15){ load_chunk(i+1, (i+1)&1); CP_WAIT(1); }
        else       { CP_WAIT(0); }
        __syncthreads();

        const uint32_t sbuf = sb0 + (i&1)*STAGE;
        #pragma unroll
        for (int kt=0; kt<2; kt++){
            const uint32_t koff = kt*32 + lcol;
            uint32_t a[4][4], bh[2][4];
            const uint32_t arow = (uint32_t)(warp_m*64 + lrow)*ROWB + koff;
            const uint32_t brow = (uint32_t)(warp_n*32 + lrow)*ROWB + koff;

            if (MODE == 0){
                // pass0: Ah (tile0) x Bh (tile2)
                #pragma unroll
                for (int mt=0; mt<4; mt++)
                    ldmx4(a[mt], sbuf + arow + (uint32_t)(mt*16)*ROWB);
                #pragma unroll
                for (int np=0; np<2; np++)
                    ldmx4(bh[np], sbuf + 2*TILE_SM + brow + (uint32_t)(np*16)*ROWB);
                #pragma unroll
                for (int mt=0; mt<4; mt++)
                    #pragma unroll
                    for (int nt=0; nt<4; nt++)
                        mma16816(acc[mt][nt], a[mt],
                                 (nt&1)?bh[nt>>1][1]:bh[nt>>1][0],
                                 (nt&1)?bh[nt>>1][3]:bh[nt>>1][2]);
                // pass1: Ah x Bl (tile3), reuse a
                {
                    uint32_t bl[2][4];
                    #pragma unroll
                    for (int np=0; np<2; np++)
                        ldmx4(bl[np], sbuf + 3*TILE_SM + brow + (uint32_t)(np*16)*ROWB);
                    #pragma unroll
                    for (int mt=0; mt<4; mt++)
                        #pragma unroll
                        for (int nt=0; nt<4; nt++)
                            mma16816(acc[mt][nt], a[mt],
                                     (nt&1)?bl[nt>>1][1]:bl[nt>>1][0],
                                     (nt&1)?bl[nt>>1][3]:bl[nt>>1][2]);
                }
                // pass2: Al (tile1) x Bh, reuse bh
                #pragma unroll
                for (int mt=0; mt<4; mt++)
                    ldmx4(a[mt], sbuf + TILE_SM + arow + (uint32_t)(mt*16)*ROWB);
                #pragma unroll
                for (int mt=0; mt<4; mt++)
                    #pragma unroll
                    for (int nt=0; nt<4; nt++)
                        mma16816(acc[mt][nt], a[mt],
                                 (nt&1)?bh[nt>>1][1]:bh[nt>>1][0],
                                 (nt&1)?bh[nt>>1][3]:bh[nt>>1][2]);
            } else {
                // B once (tile2), A twice (tiles 0, 1)
                #pragma unroll
                for (int np=0; np<2; np++)
                    ldmx4(bh[np], sbuf + 2*TILE_SM + brow + (uint32_t)(np*16)*ROWB);
                #pragma unroll
                for (int p=0; p<2; p++){
                    #pragma unroll
                    for (int mt=0; mt<4; mt++)
                        ldmx4(a[mt], sbuf + p*TILE_SM + arow + (uint32_t)(mt*16)*ROWB);
                    #pragma unroll
                    for (int mt=0; mt<4; mt++)
                        #pragma unroll
                        for (int nt=0; nt<4; nt++)
                            mma16816(acc[mt][nt], a[mt],
                                     (nt&1)?bh[nt>>1][1]:bh[nt>>1][0],
                                     (nt&1)?bh[nt>>1][3]:bh[nt>>1][2]);
                }
            }
        }
        __syncthreads();
    }

    const size_t ostride = (MODE == 0) ? 512 : THW;
    float* OutB = (MODE==0 ? g_proj + (size_t)b*THW*512 : Out + (size_t)b*512*THW);
    const float* Xb = X + (size_t)b*512*THW;
    const float* sinvb = g_sinv + b*THW;
    const int g = lane >> 2, t = lane & 3;

    #pragma unroll
    for (int mt=0; mt<4; mt++){
        #pragma unroll
        for (int nt=0; nt<4; nt++){
            int row0 = m0 + warp_m*64 + mt*16 + g;
            int col  = n0 + warp_n*32 + nt*8 + t*2;
            size_t o0 = (size_t)row0*ostride + col;
            size_t o1 = o0 + 8*ostride;
            if (MODE == 0){
                *(float2*)&OutB[o0] = make_float2(acc[mt][nt][0], acc[mt][nt][1]);
                *(float2*)&OutB[o1] = make_float2(acc[mt][nt][2], acc[mt][nt][3]);
            } else {
                float2 sv = *(const float2*)&sinvb[col];
                float2 x0 = *(const float2*)&Xb[o0];
                float2 x1 = *(const float2*)&Xb[o1];
                *(float2*)&OutB[o0] = make_float2(fmaf(acc[mt][nt][0], sv.x, x0.x),
                                                  fmaf(acc[mt][nt][1], sv.y, x0.y));
                *(float2*)&OutB[o1] = make_float2(fmaf(acc[mt][nt][2], sv.x, x1.x),
                                                  fmaf(acc[mt][nt][3], sv.y, x1.y));
            }
        }
    }
}

// ---------------- launch ----------------
extern "C" void kernel_launch(void* const* d_in, const int* in_sizes, int n_in,
                              void* d_out, int out_size)
{
    const float* x  = (const float*)d_in[0];
    const float* wr = (const float*)d_in[1];
    const float* g1 = (const float*)d_in[2];
    const float* b1 = (const float*)d_in[3];
    const float* m1 = (const float*)d_in[4];
    const float* v1 = (const float*)d_in[5];
    const float* wp = (const float*)d_in[6];
    const float* g2 = (const float*)d_in[7];
    const float* b2 = (const float*)d_in[8];
    const float* m2 = (const float*)d_in[9];
    const float* v2 = (const float*)d_in[10];
    const float* wt = (const float*)d_in[11];
    const float* g3 = (const float*)d_in[12];
    const float* b3 = (const float*)d_in[13];
    const float* m3 = (const float*)d_in[14];
    const float* v3 = (const float*)d_in[15];
    float* out = (float*)d_out;

    static int smem_set = 0;
    if (!smem_set){
        cudaFuncSetAttribute(gemm_bf16<0>, cudaFuncAttributeMaxDynamicSharedMemorySize, GSMEM0);
        cudaFuncSetAttribute(gemm_bf16<1>, cudaFuncAttributeMaxDynamicSharedMemorySize, GSMEM1);
        cudaFuncSetAttribute(k_affinity, cudaFuncAttributeMaxDynamicSharedMemorySize, AFF_SMEM);
        smem_set = 1;
    }

    k_xT<<<dim3(16, 196, BB), 256>>>(x);
    k_tp<<<dim3(7, BB), 256>>>(x, wr);
    k_tp_argmax<<<BB*RR/4, 128>>>(g1, b1, m1, v1);
    k_tresT<<<(BB*RR*CC)/256, 256>>>(x);
    k_affinity<<<dim3(49, BB), 128, AFF_SMEM>>>();
    k_topk<<<(BB*RR*TT)/4, 128>>>();
    k_traj<<<(BB*KK*CC*TT*RR)/256, 256>>>(x);
    k_fusek<<<BB*KK*TT, 256>>>(wp, g2, b2, m2, v2);
    k_maxk<<<(BB*CQ*TT*RR)/256, 256>>>();
    k_tconv<<<dim3(BB*TT, CC/16), 256>>>(wt, g3, b3, m3, v3);
    k_pointsT<<<dim3(16, 16, BB), 256>>>();
    gemm_bf16<0><<<dim3(4, 49, BB), 256, GSMEM0>>>(nullptr, nullptr);
    k_soft<<<(BB*THW)/8, 256>>>();
    gemm_bf16<1><<<dim3(49, 4, BB), 256, GSMEM1>>>(x, out);
}

// round 14
// speedup vs baseline: 1.0839x; 1.0839x over previous
#include <cuda_runtime.h>
#include <cuda_bf16.h>
#include <math.h>
#include <stdint.h>
#include <string.h>

#define BB 8
#define CC 512
#define TT 8
#define WW 28
#define HWs 784
#define THW 6272
#define RR 64
#define KK 4
#define CQ 128
#define PP 512
#define EPSC 1e-5f

// ---------------- device scratch (no allocations allowed) ----------------
__device__ __align__(256) int   g_spt[BB*RR];
__device__ __align__(256) float g_tp[BB*RR*HWs];
__device__ __align__(256) float g_aff[BB*RR*THW];
__device__ __align__(256) int   g_topk[BB*RR*TT*KK];
__device__ __align__(256) float g_traj[BB*KK*CC*TT*RR];      // (B,K,C,T,R)
__device__ __align__(256) float g_fusek[BB*KK*CQ*TT*RR];     // (B,K,Cq,T,R)
__device__ __align__(256) float g_fuse[BB*CQ*TT*RR];         // (B,Cq,T,R)
__device__ __align__(256) float g_proj[(size_t)BB*THW*PP];   // (B,S,P) logits (transposed)
__device__ __align__(256) float g_sinv[BB*THW];

// bf16 split operands (row-major [row][K])
__device__ __align__(256) __nv_bfloat16 g_trAh[BB*RR*CC];    // tresT [r][c]
__device__ __align__(256) __nv_bfloat16 g_trAl[BB*RR*CC];
__device__ __align__(256) __nv_bfloat16 g_A1h[BB*PP*CC];     // pointsT [p][c]
__device__ __align__(256) __nv_bfloat16 g_A1l[BB*PP*CC];
__device__ __align__(256) __nv_bfloat16 g_B1h[(size_t)BB*THW*CC]; // xT [s][c]
__device__ __align__(256) __nv_bfloat16 g_B1l[(size_t)BB*THW*CC];
__device__ __align__(256) __nv_bfloat16 g_A2h[BB*CC*PP];     // tc [c][p]
__device__ __align__(256) __nv_bfloat16 g_A2l[BB*CC*PP];
__device__ __align__(256) __nv_bfloat16 g_B2h[(size_t)BB*THW*PP]; // expT [s][p] (single)

// ================= sm_80-class PTX helpers ==================================
__device__ __forceinline__ uint32_t smem_u32(const void* p){
    uint32_t a;
    asm("{ .reg .u64 t; cvta.to.shared.u64 t, %1; cvt.u32.u64 %0, t; }" : "=r"(a) : "l"(p));
    return a;
}
__device__ __forceinline__ void ldmx4(uint32_t* r, uint32_t addr){
    asm volatile("ldmatrix.sync.aligned.m8n8.x4.shared.b16 {%0,%1,%2,%3}, [%4];"
                 : "=r"(r[0]), "=r"(r[1]), "=r"(r[2]), "=r"(r[3]) : "r"(addr));
}
__device__ __forceinline__ void mma16816(float* c, const uint32_t* a, uint32_t b0, uint32_t b1){
    asm volatile("mma.sync.aligned.m16n8k16.row.col.f32.bf16.bf16.f32 "
                 "{%0,%1,%2,%3}, {%4,%5,%6,%7}, {%8,%9}, {%0,%1,%2,%3};"
                 : "+f"(c[0]), "+f"(c[1]), "+f"(c[2]), "+f"(c[3])
                 : "r"(a[0]), "r"(a[1]), "r"(a[2]), "r"(a[3]), "r"(b0), "r"(b1));
}
__device__ __forceinline__ void cpa16(uint32_t s, const void* g){
    asm volatile("cp.async.cg.shared.global [%0], [%1], 16;" :: "r"(s), "l"(g));
}
#define CP_COMMIT() asm volatile("cp.async.commit_group;" ::: "memory")
#define CP_WAIT(N)  asm volatile("cp.async.wait_group %0;" :: "n"(N) : "memory")

__device__ __forceinline__ uint32_t pack_bf16(__nv_bfloat16 lo, __nv_bfloat16 hi){
    uint16_t ul, uh;
    memcpy(&ul, &lo, 2); memcpy(&uh, &hi, 2);
    return (uint32_t)ul | ((uint32_t)uh << 16);
}
__device__ __forceinline__ void split_bf(float v, __nv_bfloat16& h, __nv_bfloat16& l){
    h = __float2bfloat16(v);
    l = __float2bfloat16(v - __bfloat162float(h));
}

// ---------------- 1a: g_tp[b][r][s] = (w_reduce @ x[:,:,0,:])[r][s]
__global__ void __launch_bounds__(256) k_tp(const float* __restrict__ x,
                                            const float* __restrict__ wr)
{
    int b = blockIdx.y;
    int s0 = blockIdx.x * 112;
    __shared__ float ws[32][65];
    __shared__ float xs[32][113];
    int tid = threadIdx.x;
    int tx = tid & 15, ty = tid >> 4;
    float acc[4][7];
    #pragma unroll
    for (int i=0;i<4;i++)
        #pragma unroll
        for (int j=0;j<7;j++) acc[i][j]=0.f;

    for (int cc = 0; cc < CC; cc += 32){
        #pragma unroll
        for (int it=0; it<8; it++){
            int id = tid + it*256;
            int r = id >> 5, k = id & 31;
            ws[k][r] = wr[r*CC + cc + k];
        }
        #pragma unroll
        for (int it=0; it<14; it++){
            int id = tid + it*256;
            int k = id / 112, s = id % 112;
            xs[k][s] = x[(size_t)(b*CC + cc + k)*THW + s0 + s];
        }
        __syncthreads();
        #pragma unroll 4
        for (int k=0;k<32;k++){
            float a[4], bv[7];
            #pragma unroll
            for (int i=0;i<4;i++) a[i] = ws[k][ty*4+i];
            #pragma unroll
            for (int j=0;j<7;j++) bv[j] = xs[k][tx*7+j];
            #pragma unroll
            for (int i=0;i<4;i++)
                #pragma unroll
                for (int j=0;j<7;j++) acc[i][j] += a[i]*bv[j];
        }
        __syncthreads();
    }
    #pragma unroll
    for (int i=0;i<4;i++)
        #pragma unroll
        for (int j=0;j<7;j++)
            g_tp[(b*RR + ty*4+i)*HWs + s0 + tx*7 + j] = acc[i][j];
}

// ---------------- 1b: argmax over HW of bn1(g_tp)
__global__ void k_tp_argmax(const float* __restrict__ g1, const float* __restrict__ b1,
                            const float* __restrict__ m1, const float* __restrict__ v1)
{
    int w = blockIdx.x*4 + (threadIdx.x >> 5);
    int lane = threadIdx.x & 31;
    int r = w & 63;
    float scale = g1[r] * rsqrtf(v1[r] + EPSC);
    float shift = b1[r] - m1[r]*scale;
    const float* row = g_tp + (size_t)w*HWs;
    float best = -3.4e38f; int bi = 0;
    #pragma unroll
    for (int i=0;i<25;i++){
        int idx = i*32 + lane;
        if (idx < HWs){
            float v = row[idx]*scale + shift;
            if (v > best){ best = v; bi = idx; }
        }
    }
    #pragma unroll
    for (int off=16; off; off>>=1){
        float ov = __shfl_down_sync(0xffffffffu, best, off);
        int oi = __shfl_down_sync(0xffffffffu, bi, off);
        if (ov > best || (ov == best && oi < bi)){ best = ov; bi = oi; }
    }
    if (lane == 0) g_spt[w] = bi;
}

// ---------------- 2: template_resample gather -> bf16 split [b][r][c]
__global__ void k_tresT(const float* __restrict__ x){
    int o = blockIdx.x*256 + threadIdx.x;
    int c = o & 511; int r = (o>>9) & 63; int b = o >> 15;
    int idx = g_spt[b*RR + r];
    float v = x[(size_t)(b*CC + c)*THW + idx];
    __nv_bfloat16 h, l; split_bf(v, h, l);
    g_trAh[o] = h; g_trAl[o] = l;
}

// ================= HMMA affinity: M=64, N=6272, K=512, 3-pass bf16 =========
#define ROWB   80
#define AF_STAGE (384*ROWB)       // 30720
#define AFF_SMEM (2*AF_STAGE)     // 61440

__global__ void __launch_bounds__(128, 3) k_affinity(){
    extern __shared__ char smem[];
    const uint32_t sb0 = smem_u32(smem);
    const int tid = threadIdx.x;
    const int wid = tid >> 5, lane = tid & 31;

    const int n0 = blockIdx.x * 128;
    const int b  = blockIdx.y;

    const __nv_bfloat16* Ah = g_trAh + (size_t)b*RR*512;
    const __nv_bfloat16* Al = g_trAl + (size_t)b*RR*512;
    const __nv_bfloat16* Bh = g_B1h + ((size_t)b*THW + n0)*512;
    const __nv_bfloat16* Bl = g_B1l + ((size_t)b*THW + n0)*512;

    float acc[4][4][4];
    #pragma unroll
    for (int i=0;i<4;i++)
        #pragma unroll
        for (int j=0;j<4;j++)
            #pragma unroll
            for (int q=0;q<4;q++) acc[i][j][q]=0.f;

    const int lrow = (lane & 7) + ((lane >> 3) & 1) * 8;
    const int lcol = (lane >> 4) * 16;

    auto load_chunk = [&](int i, int buf){
        uint32_t sbase = sb0 + buf*AF_STAGE;
        #pragma unroll
        for (int it=0; it<12; it++){
            int id = tid + it*128;           // 0..1535
            int row = id >> 2, c = id & 3;
            const __nv_bfloat16* g;
            if (row < 128) g = (row < 64 ? Ah : Al) + (size_t)(row & 63)*512;
            else           g = (row < 256 ? Bh : Bl) + (size_t)((row - 128) & 127)*512;
            cpa16(sbase + row*ROWB + c*16, g + i*32 + c*8);
        }
        CP_COMMIT();
    };

    load_chunk(0, 0);

    for (int i = 0; i < 16; i++){
        if (i < 15){ load_chunk(i+1, (i+1)&1); CP_WAIT(1); }
        else       { CP_WAIT(0); }
        __syncthreads();

        const uint32_t sbuf = sb0 + (i&1)*AF_STAGE;
        #pragma unroll
        for (int kt=0; kt<2; kt++){
            const uint32_t koff = kt*32 + lcol;
            uint32_t a[4][4], bh[2][4], bl[2][4];
            #pragma unroll
            for (int mt=0; mt<4; mt++)
                ldmx4(a[mt], sbuf + (uint32_t)(mt*16 + lrow)*ROWB + koff);
            #pragma unroll
            for (int np=0; np<2; np++)
                ldmx4(bh[np], sbuf + 128*ROWB + (uint32_t)(wid*32 + np*16 + lrow)*ROWB + koff);
            #pragma unroll
            for (int mt=0; mt<4; mt++)
                #pragma unroll
                for (int nt=0; nt<4; nt++)
                    mma16816(acc[mt][nt], a[mt],
                             (nt&1)?bh[nt>>1][1]:bh[nt>>1][0],
                             (nt&1)?bh[nt>>1][3]:bh[nt>>1][2]);
            #pragma unroll
            for (int np=0; np<2; np++)
                ldmx4(bl[np], sbuf + 256*ROWB + (uint32_t)(wid*32 + np*16 + lrow)*ROWB + koff);
            #pragma unroll
            for (int mt=0; mt<4; mt++)
                #pragma unroll
                for (int nt=0; nt<4; nt++)
                    mma16816(acc[mt][nt], a[mt],
                             (nt&1)?bl[nt>>1][1]:bl[nt>>1][0],
                             (nt&1)?bl[nt>>1][3]:bl[nt>>1][2]);
            #pragma unroll
            for (int mt=0; mt<4; mt++)
                ldmx4(a[mt], sbuf + 64*ROWB + (uint32_t)(mt*16 + lrow)*ROWB + koff);
            #pragma unroll
            for (int mt=0; mt<4; mt++)
                #pragma unroll
                for (int nt=0; nt<4; nt++)
                    mma16816(acc[mt][nt], a[mt],
                             (nt&1)?bh[nt>>1][1]:bh[nt>>1][0],
                             (nt&1)?bh[nt>>1][3]:bh[nt>>1][2]);
        }
        __syncthreads();
    }

    const int g = lane >> 2, t = lane & 3;
    float* OutB = g_aff + (size_t)b*RR*THW;
    #pragma unroll
    for (int mt=0; mt<4; mt++){
        #pragma unroll
        for (int nt=0; nt<4; nt++){
            int row0 = mt*16 + g;
            int col  = n0 + wid*32 + nt*8 + t*2;
            size_t o0 = (size_t)row0*THW + col;
            size_t o1 = o0 + (size_t)8*THW;
            *(float2*)&OutB[o0] = make_float2(acc[mt][nt][0], acc[mt][nt][1]);
            *(float2*)&OutB[o1] = make_float2(acc[mt][nt][2], acc[mt][nt][3]);
        }
    }
}

// ---------------- 4: top-4 over HW per (b,r,t)
__global__ void k_topk(){
    int w = blockIdx.x*4 + (threadIdx.x >> 5);
    int lane = threadIdx.x & 31;
    const float* row = g_aff + (size_t)(w >> 3)*THW + (w & 7)*HWs;
    float lv[25];
    #pragma unroll
    for (int i=0;i<25;i++){
        int idx = i*32 + lane;
        lv[i] = (idx < HWs) ? row[idx] : -3.4e38f;
    }
    for (int kq=0;kq<KK;kq++){
        float v = -3.4e38f; int pos = 0;
        #pragma unroll
        for (int i=0;i<25;i++) if (lv[i] > v){ v = lv[i]; pos = i; }
        int gi = pos*32 + lane;
        #pragma unroll
        for (int off=16; off; off>>=1){
            float ov = __shfl_down_sync(0xffffffffu, v, off);
            int oi = __shfl_down_sync(0xffffffffu, gi, off);
            if (ov > v || (ov == v && oi < gi)){ v = ov; gi = oi; }
        }
        gi = __shfl_sync(0xffffffffu, gi, 0);
        #pragma unroll
        for (int i=0;i<25;i++) if (i*32 + lane == gi) lv[i] = -3.4e38f;
        if (lane == 0) g_topk[w*KK + kq] = gi;
    }
}

// ---------------- 5: trajectory gather
__global__ void k_traj(const float* __restrict__ x){
    int o = blockIdx.x*256 + threadIdx.x;
    int r = o & 63, t = (o>>6)&7, c = (o>>9)&511, kq = (o>>18)&3, b = o>>20;
    int idx = g_topk[((b*RR + r)*TT + t)*KK + kq];
    g_traj[o] = x[((size_t)(b*CC + c)*TT + t)*HWs + idx];
}

// ---------------- 6: per-k projection
__global__ void __launch_bounds__(256) k_fusek(
    const float* __restrict__ wp,
    const float* __restrict__ g2, const float* __restrict__ b2,
    const float* __restrict__ m2, const float* __restrict__ v2)
{
    int blk = blockIdx.x;
    int b = blk >> 5, ks = (blk >> 3) & 3, t = blk & 7;
    int tid = threadIdx.x, tx = tid & 15, ty = tid >> 4;
    __shared__ float As[32][132];
    __shared__ float Bs[32][64];
    float acc[8][4];
    #pragma unroll
    for (int i=0;i<8;i++){
        #pragma unroll
        for (int j=0;j<4;j++) acc[i][j]=0.f;
    }
    const float* Tb = g_traj + (size_t)(b*KK + ks)*CC*(TT*RR) + t*RR;
    for (int cc = 0; cc < CC; cc += 32){
        #pragma unroll
        for (int i=0;i<16;i++){
            int l = tid + 256*i;
            int k = l & 31, m = l >> 5;
            As[k][m] = wp[m*514 + cc + k];
        }
        #pragma unroll
        for (int i=0;i<8;i++){
            int l = tid + 256*i;
            int n = l & 63, k = l >> 6;
            Bs[k][n] = Tb[(size_t)(cc + k)*(TT*RR) + n];
        }
        __syncthreads();
        #pragma unroll
        for (int k=0;k<32;k++){
            float4 a0 = *(const float4*)&As[k][ty*4];
            float4 a1 = *(const float4*)&As[k][64 + ty*4];
            float4 bv = *(const float4*)&Bs[k][tx*4];
            float av[8] = {a0.x,a0.y,a0.z,a0.w,a1.x,a1.y,a1.z,a1.w};
            float bw[4] = {bv.x,bv.y,bv.z,bv.w};
            #pragma unroll
            for (int i=0;i<8;i++){
                #pragma unroll
                for (int j=0;j<4;j++) acc[i][j] += av[i]*bw[j];
            }
        }
        __syncthreads();
    }
    #pragma unroll
    for (int j=0;j<4;j++){
        int r = tx*4 + j;
        int idx = g_topk[((b*RR + r)*TT + t)*KK + ks];
        float rv = (float)(idx / WW) * (1.f/28.f);
        float cv = (float)(idx % WW) * (1.f/28.f);
        #pragma unroll
        for (int i=0;i<8;i++){
            int q = (i<4) ? ty*4+i : 64 + ty*4 + i - 4;
            acc[i][j] += wp[q*514 + 512]*rv + wp[q*514 + 513]*cv;
        }
    }
    #pragma unroll
    for (int i=0;i<8;i++){
        int q = (i<4) ? ty*4+i : 64 + ty*4 + i - 4;
        float sc = g2[q]*rsqrtf(v2[q]+EPSC);
        float sh = b2[q] - m2[q]*sc;
        #pragma unroll
        for (int j=0;j<4;j++){
            int r = tx*4+j;
            g_fusek[((size_t)(b*KK+ks)*CQ + q)*(TT*RR) + t*RR + r] = acc[i][j]*sc + sh;
        }
    }
}

// ---------------- 7: max over k
__global__ void k_maxk(){
    int o = blockIdx.x*256 + threadIdx.x;
    int b = o >> 16, rem = o & 65535;
    float m = g_fusek[(size_t)(b*KK)*65536 + rem];
    #pragma unroll
    for (int ks=1; ks<KK; ks++)
        m = fmaxf(m, g_fusek[(size_t)(b*KK+ks)*65536 + rem]);
    g_fuse[o] = m;
}

// ---------------- 8: temporal conv + bn3 + relu -> A2 bf16 split
__global__ void __launch_bounds__(256) k_tconv(
    const float* __restrict__ wt,
    const float* __restrict__ g3, const float* __restrict__ b3,
    const float* __restrict__ m3, const float* __restrict__ v3)
{
    int b = blockIdx.x >> 3, t = blockIdx.x & 7;
    int coBase = blockIdx.y * 16;
    int r = threadIdx.x & 63;
    int g = threadIdx.x >> 6;
    float acc[4] = {0.f,0.f,0.f,0.f};
    const float* fbase = g_fuse + (size_t)b*CQ*(TT*RR);
    for (int ci=0; ci<CQ; ci++){
        #pragma unroll
        for (int j=0;j<3;j++){
            int tt = t + j - 1;
            if (tt < 0 || tt >= TT) continue;
            float f = fbase[ci*(TT*RR) + tt*RR + r];
            #pragma unroll
            for (int cc=0; cc<4; cc++){
                int co = coBase + g*4 + cc;
                acc[cc] += wt[(co*CQ + ci)*3 + j] * f;
            }
        }
    }
    #pragma unroll
    for (int cc=0; cc<4; cc++){
        int co = coBase + g*4 + cc;
        float sc = g3[co]*rsqrtf(v3[co]+EPSC);
        float sh = b3[co] - m3[co]*sc;
        float v = fmaxf(acc[cc]*sc + sh, 0.f);
        size_t o = (size_t)(b*CC + co)*(TT*RR) + t*RR + r;
        __nv_bfloat16 h, l; split_bf(v, h, l);
        g_A2h[o] = h; g_A2l[o] = l;
    }
}

// ---------------- 9: points (mean over k of traj) transposed + bf16 split
__global__ void __launch_bounds__(256) k_pointsT(){
    __shared__ float s[32][33];
    int ct = blockIdx.x, pt = blockIdx.y, b = blockIdx.z;
    int t = threadIdx.x;
    int rr = t >> 5, cl = t & 31;
    #pragma unroll
    for (int it=0; it<4; it++){
        int c = ct*32 + it*8 + rr;
        size_t base = ((size_t)c << 9) + pt*32 + cl;
        float sm = 0.f;
        #pragma unroll
        for (int k=0;k<KK;k++) sm += g_traj[(((size_t)(b*KK+k))<<18) + base];
        s[it*8+rr][cl] = sm * 0.25f;
    }
    __syncthreads();
    #pragma unroll
    for (int it=0; it<4; it++){
        int pl = it*8 + rr;
        float v = s[cl][pl];
        size_t o = ((size_t)(b*PP) + pt*32 + pl)*CC + ct*32 + cl;
        __nv_bfloat16 h, l; split_bf(v, h, l);
        g_A1h[o] = h; g_A1l[o] = l;
    }
}

// ---------------- 10: x transpose + split: B1[b][s][c] = x[b][c][s]
__global__ void __launch_bounds__(256) k_xT(const float* __restrict__ x){
    __shared__ float s[32][33];
    int ct = blockIdx.x, st = blockIdx.y, b = blockIdx.z;
    int t = threadIdx.x;
    int rr = t >> 5, cl = t & 31;
    #pragma unroll
    for (int it=0; it<4; it++){
        int c = ct*32 + it*8 + rr;
        s[it*8+rr][cl] = x[((size_t)(b*CC) + c)*THW + st*32 + cl];
    }
    __syncthreads();
    #pragma unroll
    for (int it=0; it<2; it++){
        int id = t + it*256;
        int sl = id >> 4;
        int cp = id & 15;
        float v0 = s[cp*2][sl];
        float v1 = s[cp*2+1][sl];
        __nv_bfloat16 h0,l0,h1,l1;
        split_bf(v0, h0, l0); split_bf(v1, h1, l1);
        size_t o = ((size_t)b*THW + st*32 + sl)*CC + ct*32 + cp*2;
        *(uint32_t*)&g_B1h[o] = pack_bf16(h0, h1);
        *(uint32_t*)&g_B1l[o] = pack_bf16(l0, l1);
    }
}

// ---------------- 11: row softmax on projT [s][p] -> B2 bf16 + sinv
__global__ void __launch_bounds__(256) k_soft(){
    int w = blockIdx.x*8 + (threadIdx.x >> 5);     // 0..BB*THW-1
    int lane = threadIdx.x & 31;
    const float* pr = g_proj + (size_t)w*PP;
    float v[16];
    #pragma unroll
    for (int j=0;j<4;j++){
        float4 t = *(const float4*)&pr[j*128 + lane*4];
        v[j*4+0]=t.x; v[j*4+1]=t.y; v[j*4+2]=t.z; v[j*4+3]=t.w;
    }
    float mx = v[0];
    #pragma unroll
    for (int i=1;i<16;i++) mx = fmaxf(mx, v[i]);
    #pragma unroll
    for (int off=16; off; off>>=1) mx = fmaxf(mx, __shfl_xor_sync(0xffffffffu, mx, off));
    float sm = 0.f;
    #pragma unroll
    for (int i=0;i<16;i++){ v[i] = __expf(v[i] - mx); sm += v[i]; }
    #pragma unroll
    for (int off=16; off; off>>=1) sm += __shfl_xor_sync(0xffffffffu, sm, off);
    if (lane == 0) g_sinv[w] = 1.f / sm;

    #pragma unroll
    for (int j=0;j<4;j++){
        __nv_bfloat16 h0 = __float2bfloat16(v[j*4+0]);
        __nv_bfloat16 h1 = __float2bfloat16(v[j*4+1]);
        __nv_bfloat16 h2 = __float2bfloat16(v[j*4+2]);
        __nv_bfloat16 h3 = __float2bfloat16(v[j*4+3]);
        size_t o = (size_t)w*PP + j*128 + lane*4;
        *(uint2*)&g_B2h[o] = make_uint2(pack_bf16(h0, h1), pack_bf16(h2, h3));
    }
}

// ================= HMMA GEMM 128x128, 256 thr ==============================
// MODE 0: projT[s][p] = xT @ pointsT^T   3-pass, 4 tiles (both splits)
// MODE 1: out = x + (tc @ expT^T)*sinv   2-pass, 3 tiles (A split, B single)
#define TILE_SM (128*ROWB)        // 10240
#define GSMEM0 (2*4*TILE_SM)      // 81920
#define GSMEM1 (2*3*TILE_SM)      // 61440

template<int MODE>
__global__ void __launch_bounds__(256, 2)
gemm_bf16(const float* __restrict__ X, float* __restrict__ Out)
{
    constexpr int NT = (MODE==0) ? 4 : 3;
    constexpr int STAGE = NT*TILE_SM;

    extern __shared__ char smem[];
    const uint32_t sb0 = smem_u32(smem);
    const int tid = threadIdx.x;
    const int wid = tid >> 5, lane = tid & 31;
    const int warp_m = wid >> 2, warp_n = wid & 3;

    const int n0 = blockIdx.x * 128;
    const int m0 = blockIdx.y * 128;
    const int b  = blockIdx.z;

    const __nv_bfloat16* tp[NT];
    if (MODE == 0){
        tp[0] = g_B1h + ((size_t)b*THW + m0)*512;
        tp[1] = g_B1l + ((size_t)b*THW + m0)*512;
        tp[2] = g_A1h + ((size_t)(b*512) + n0)*512;
        tp[3] = g_A1l + ((size_t)(b*512) + n0)*512;
    } else {
        tp[0] = g_A2h + ((size_t)(b*512) + m0)*512;
        tp[1] = g_A2l + ((size_t)(b*512) + m0)*512;
        tp[2] = g_B2h + ((size_t)b*THW + n0)*512;
    }

    float acc[4][4][4];
    #pragma unroll
    for (int i=0;i<4;i++)
        #pragma unroll
        for (int j=0;j<4;j++)
            #pragma unroll
            for (int q=0;q<4;q++) acc[i][j][q]=0.f;

    const int lrow = (lane & 7) + ((lane >> 3) & 1) * 8;
    const int lcol = (lane >> 4) * 16;

    auto load_chunk = [&](int i, int buf){
        uint32_t sbase = sb0 + buf*STAGE;
        #pragma unroll
        for (int it=0; it<2*NT; it++){
            int id = tid + it*256;
            int row = id >> 2, c = id & 3;
            int tile = row >> 7, rowin = row & 127;
            const __nv_bfloat16* g = tp[tile] + (size_t)rowin*512 + i*32 + c*8;
            cpa16(sbase + tile*TILE_SM + rowin*ROWB + c*16, g);
        }
        CP_COMMIT();
    };

    load_chunk(0, 0);

    for (int i = 0; i < 16; i++){
        if (i < 15){ load_chunk(i+1, (i+1)&1); CP_WAIT(1); }
        else       { CP_WAIT(0); }
        __syncthreads();

        const uint32_t sbuf = sb0 + (i&1)*STAGE;
        #pragma unroll
        for (int kt=0; kt<2; kt++){
            const uint32_t koff = kt*32 + lcol;
            uint32_t a[4][4], bh[2][4];
            const uint32_t arow = (uint32_t)(warp_m*64 + lrow)*ROWB + koff;
            const uint32_t brow = (uint32_t)(warp_n*32 + lrow)*ROWB + koff;

            if (MODE == 0){
                #pragma unroll
                for (int mt=0; mt<4; mt++)
                    ldmx4(a[mt], sbuf + arow + (uint32_t)(mt*16)*ROWB);
                #pragma unroll
                for (int np=0; np<2; np++)
                    ldmx4(bh[np], sbuf + 2*TILE_SM + brow + (uint32_t)(np*16)*ROWB);
                #pragma unroll
                for (int mt=0; mt<4; mt++)
                    #pragma unroll
                    for (int nt=0; nt<4; nt++)
                        mma16816(acc[mt][nt], a[mt],
                                 (nt&1)?bh[nt>>1][1]:bh[nt>>1][0],
                                 (nt&1)?bh[nt>>1][3]:bh[nt>>1][2]);
                {
                    uint32_t bl[2][4];
                    #pragma unroll
                    for (int np=0; np<2; np++)
                        ldmx4(bl[np], sbuf + 3*TILE_SM + brow + (uint32_t)(np*16)*ROWB);
                    #pragma unroll
                    for (int mt=0; mt<4; mt++)
                        #pragma unroll
                        for (int nt=0; nt<4; nt++)
                            mma16816(acc[mt][nt], a[mt],
                                     (nt&1)?bl[nt>>1][1]:bl[nt>>1][0],
                                     (nt&1)?bl[nt>>1][3]:bl[nt>>1][2]);
                }
                #pragma unroll
                for (int mt=0; mt<4; mt++)
                    ldmx4(a[mt], sbuf + TILE_SM + arow + (uint32_t)(mt*16)*ROWB);
                #pragma unroll
                for (int mt=0; mt<4; mt++)
                    #pragma unroll
                    for (int nt=0; nt<4; nt++)
                        mma16816(acc[mt][nt], a[mt],
                                 (nt&1)?bh[nt>>1][1]:bh[nt>>1][0],
                                 (nt&1)?bh[nt>>1][3]:bh[nt>>1][2]);
            } else {
                #pragma unroll
                for (int np=0; np<2; np++)
                    ldmx4(bh[np], sbuf + 2*TILE_SM + brow + (uint32_t)(np*16)*ROWB);
                #pragma unroll
                for (int p=0; p<2; p++){
                    #pragma unroll
                    for (int mt=0; mt<4; mt++)
                        ldmx4(a[mt], sbuf + p*TILE_SM + arow + (uint32_t)(mt*16)*ROWB);
                    #pragma unroll
                    for (int mt=0; mt<4; mt++)
                        #pragma unroll
                        for (int nt=0; nt<4; nt++)
                            mma16816(acc[mt][nt], a[mt],
                                     (nt&1)?bh[nt>>1][1]:bh[nt>>1][0],
                                     (nt&1)?bh[nt>>1][3]:bh[nt>>1][2]);
                }
            }
        }
        __syncthreads();
    }

    const size_t ostride = (MODE == 0) ? 512 : THW;
    float* OutB = (MODE==0 ? g_proj + (size_t)b*THW*512 : Out + (size_t)b*512*THW);
    const float* Xb = X + (size_t)b*512*THW;
    const float* sinvb = g_sinv + b*THW;
    const int g = lane >> 2, t = lane & 3;

    #pragma unroll
    for (int mt=0; mt<4; mt++){
        #pragma unroll
        for (int nt=0; nt<4; nt++){
            int row0 = m0 + warp_m*64 + mt*16 + g;
            int col  = n0 + warp_n*32 + nt*8 + t*2;
            size_t o0 = (size_t)row0*ostride + col;
            size_t o1 = o0 + 8*ostride;
            if (MODE == 0){
                *(float2*)&OutB[o0] = make_float2(acc[mt][nt][0], acc[mt][nt][1]);
                *(float2*)&OutB[o1] = make_float2(acc[mt][nt][2], acc[mt][nt][3]);
            } else {
                float2 sv = *(const float2*)&sinvb[col];
                float2 x0 = *(const float2*)&Xb[o0];
                float2 x1 = *(const float2*)&Xb[o1];
                *(float2*)&OutB[o0] = make_float2(fmaf(acc[mt][nt][0], sv.x, x0.x),
                                                  fmaf(acc[mt][nt][1], sv.y, x0.y));
                *(float2*)&OutB[o1] = make_float2(fmaf(acc[mt][nt][2], sv.x, x1.x),
                                                  fmaf(acc[mt][nt][3], sv.y, x1.y));
            }
        }
    }
}

// ---------------- launch (stream fork/join for overlap) ----------------
extern "C" void kernel_launch(void* const* d_in, const int* in_sizes, int n_in,
                              void* d_out, int out_size)
{
    const float* x  = (const float*)d_in[0];
    const float* wr = (const float*)d_in[1];
    const float* g1 = (const float*)d_in[2];
    const float* b1 = (const float*)d_in[3];
    const float* m1 = (const float*)d_in[4];
    const float* v1 = (const float*)d_in[5];
    const float* wp = (const float*)d_in[6];
    const float* g2 = (const float*)d_in[7];
    const float* b2 = (const float*)d_in[8];
    const float* m2 = (const float*)d_in[9];
    const float* v2 = (const float*)d_in[10];
    const float* wt = (const float*)d_in[11];
    const float* g3 = (const float*)d_in[12];
    const float* b3 = (const float*)d_in[13];
    const float* m3 = (const float*)d_in[14];
    const float* v3 = (const float*)d_in[15];
    float* out = (float*)d_out;

    static cudaStream_t s1 = nullptr;
    static cudaEvent_t evF1, evJ1, evF2, evJ2;
    static int inited = 0;
    if (!inited){
        cudaStreamCreateWithFlags(&s1, cudaStreamNonBlocking);
        cudaEventCreateWithFlags(&evF1, cudaEventDisableTiming);
        cudaEventCreateWithFlags(&evJ1, cudaEventDisableTiming);
        cudaEventCreateWithFlags(&evF2, cudaEventDisableTiming);
        cudaEventCreateWithFlags(&evJ2, cudaEventDisableTiming);
        cudaFuncSetAttribute(gemm_bf16<0>, cudaFuncAttributeMaxDynamicSharedMemorySize, GSMEM0);
        cudaFuncSetAttribute(gemm_bf16<1>, cudaFuncAttributeMaxDynamicSharedMemorySize, GSMEM1);
        cudaFuncSetAttribute(k_affinity, cudaFuncAttributeMaxDynamicSharedMemorySize, AFF_SMEM);
        inited = 1;
    }

    // ---- fork 1: template chain on s1, xT on main ----
    cudaEventRecord(evF1, 0);
    cudaStreamWaitEvent(s1, evF1, 0);
    k_tp<<<dim3(7, BB), 256, 0, s1>>>(x, wr);
    k_tp_argmax<<<BB*RR/4, 128, 0, s1>>>(g1, b1, m1, v1);
    k_tresT<<<(BB*RR*CC)/256, 256, 0, s1>>>(x);
    cudaEventRecord(evJ1, s1);

    k_xT<<<dim3(16, 196, BB), 256>>>(x);
    cudaStreamWaitEvent(0, evJ1, 0);

    // ---- serial: affinity -> topk -> traj ----
    k_affinity<<<dim3(49, BB), 128, AFF_SMEM>>>();
    k_topk<<<(BB*RR*TT)/4, 128>>>();
    k_traj<<<(BB*KK*CC*TT*RR)/256, 256>>>(x);

    // ---- fork 2: fusek->maxk->tconv on s1, pointsT->gemm0->soft on main ----
    cudaEventRecord(evF2, 0);
    cudaStreamWaitEvent(s1, evF2, 0);
    k_fusek<<<BB*KK*TT, 256, 0, s1>>>(wp, g2, b2, m2, v2);
    k_maxk<<<(BB*CQ*TT*RR)/256, 256, 0, s1>>>();
    k_tconv<<<dim3(BB*TT, CC/16), 256, 0, s1>>>(wt, g3, b3, m3, v3);
    cudaEventRecord(evJ2, s1);

    k_pointsT<<<dim3(16, 16, BB), 256>>>();
    gemm_bf16<0><<<dim3(4, 49, BB), 256, GSMEM0>>>(nullptr, nullptr);
    k_soft<<<(BB*THW)/8, 256>>>();
    cudaStreamWaitEvent(0, evJ2, 0);

    gemm_bf16<1><<<dim3(49, 4, BB), 256, GSMEM1>>>(x, out);
}

// round 15
// speedup vs baseline: 1.0973x; 1.0124x over previous
#include <cuda_runtime.h>
#include <cuda_bf16.h>
#include <math.h>
#include <stdint.h>
#include <string.h>

#define BB 8
#define CC 512
#define TT 8
#define WW 28
#define HWs 784
#define THW 6272
#define RR 64
#define KK 4
#define CQ 128
#define PP 512
#define EPSC 1e-5f

// ---------------- device scratch (no allocations allowed) ----------------
__device__ __align__(256) int   g_spt[BB*RR];
__device__ __align__(256) float g_tp[BB*RR*HWs];
__device__ __align__(256) float g_aff[BB*RR*THW];
__device__ __align__(256) int   g_topk[BB*RR*TT*KK];
__device__ __align__(256) float g_traj[BB*KK*CC*TT*RR];      // (B,K,C,T,R)
__device__ __align__(256) float g_fusek[BB*KK*CQ*TT*RR];     // (B,K,Cq,T,R)
__device__ __align__(256) float g_fuse[BB*CQ*TT*RR];         // (B,Cq,T,R)
__device__ __align__(256) float g_proj[(size_t)BB*THW*PP];   // (B,S,P) logits (transposed)
__device__ __align__(256) float g_sinv[BB*THW];

// bf16 split operands (row-major [row][K])
__device__ __align__(256) __nv_bfloat16 g_trAh[BB*RR*CC];    // tresT [r][c]
__device__ __align__(256) __nv_bfloat16 g_trAl[BB*RR*CC];
__device__ __align__(256) __nv_bfloat16 g_A1h[BB*PP*CC];     // pointsT [p][c]
__device__ __align__(256) __nv_bfloat16 g_A1l[BB*PP*CC];
__device__ __align__(256) __nv_bfloat16 g_B1h[(size_t)BB*THW*CC]; // xT [s][c]
__device__ __align__(256) __nv_bfloat16 g_B1l[(size_t)BB*THW*CC];
__device__ __align__(256) __nv_bfloat16 g_A2h[BB*CC*PP];     // tc [c][p]
__device__ __align__(256) __nv_bfloat16 g_A2l[BB*CC*PP];
__device__ __align__(256) __nv_bfloat16 g_B2h[(size_t)BB*THW*PP]; // expT [s][p] (single)

// ================= sm_80-class PTX helpers ==================================
__device__ __forceinline__ uint32_t smem_u32(const void* p){
    uint32_t a;
    asm("{ .reg .u64 t; cvta.to.shared.u64 t, %1; cvt.u32.u64 %0, t; }" : "=r"(a) : "l"(p));
    return a;
}
__device__ __forceinline__ void ldmx4(uint32_t* r, uint32_t addr){
    asm volatile("ldmatrix.sync.aligned.m8n8.x4.shared.b16 {%0,%1,%2,%3}, [%4];"
                 : "=r"(r[0]), "=r"(r[1]), "=r"(r[2]), "=r"(r[3]) : "r"(addr));
}
__device__ __forceinline__ void mma16816(float* c, const uint32_t* a, uint32_t b0, uint32_t b1){
    asm volatile("mma.sync.aligned.m16n8k16.row.col.f32.bf16.bf16.f32 "
                 "{%0,%1,%2,%3}, {%4,%5,%6,%7}, {%8,%9}, {%0,%1,%2,%3};"
                 : "+f"(c[0]), "+f"(c[1]), "+f"(c[2]), "+f"(c[3])
                 : "r"(a[0]), "r"(a[1]), "r"(a[2]), "r"(a[3]), "r"(b0), "r"(b1));
}
__device__ __forceinline__ void cpa16(uint32_t s, const void* g){
    asm volatile("cp.async.cg.shared.global [%0], [%1], 16;" :: "r"(s), "l"(g));
}
#define CP_COMMIT() asm volatile("cp.async.commit_group;" ::: "memory")
#define CP_WAIT(N)  asm volatile("cp.async.wait_group %0;" :: "n"(N) : "memory")

__device__ __forceinline__ uint32_t pack_bf16(__nv_bfloat16 lo, __nv_bfloat16 hi){
    uint16_t ul, uh;
    memcpy(&ul, &lo, 2); memcpy(&uh, &hi, 2);
    return (uint32_t)ul | ((uint32_t)uh << 16);
}
__device__ __forceinline__ void split_bf(float v, __nv_bfloat16& h, __nv_bfloat16& l){
    h = __float2bfloat16(v);
    l = __float2bfloat16(v - __bfloat162float(h));
}

// ---------------- 1a: g_tp[b][r][s] = (w_reduce @ x[:,:,0,:])[r][s]
__global__ void __launch_bounds__(256) k_tp(const float* __restrict__ x,
                                            const float* __restrict__ wr)
{
    int b = blockIdx.y;
    int s0 = blockIdx.x * 112;
    __shared__ float ws[32][65];
    __shared__ float xs[32][113];
    int tid = threadIdx.x;
    int tx = tid & 15, ty = tid >> 4;
    float acc[4][7];
    #pragma unroll
    for (int i=0;i<4;i++)
        #pragma unroll
        for (int j=0;j<7;j++) acc[i][j]=0.f;

    for (int cc = 0; cc < CC; cc += 32){
        #pragma unroll
        for (int it=0; it<8; it++){
            int id = tid + it*256;
            int r = id >> 5, k = id & 31;
            ws[k][r] = wr[r*CC + cc + k];
        }
        #pragma unroll
        for (int it=0; it<14; it++){
            int id = tid + it*256;
            int k = id / 112, s = id % 112;
            xs[k][s] = x[(size_t)(b*CC + cc + k)*THW + s0 + s];
        }
        __syncthreads();
        #pragma unroll 4
        for (int k=0;k<32;k++){
            float a[4], bv[7];
            #pragma unroll
            for (int i=0;i<4;i++) a[i] = ws[k][ty*4+i];
            #pragma unroll
            for (int j=0;j<7;j++) bv[j] = xs[k][tx*7+j];
            #pragma unroll
            for (int i=0;i<4;i++)
                #pragma unroll
                for (int j=0;j<7;j++) acc[i][j] += a[i]*bv[j];
        }
        __syncthreads();
    }
    #pragma unroll
    for (int i=0;i<4;i++)
        #pragma unroll
        for (int j=0;j<7;j++)
            g_tp[(b*RR + ty*4+i)*HWs + s0 + tx*7 + j] = acc[i][j];
}

// ---------------- 1b: argmax over HW of bn1(g_tp)
__global__ void k_tp_argmax(const float* __restrict__ g1, const float* __restrict__ b1,
                            const float* __restrict__ m1, const float* __restrict__ v1)
{
    int w = blockIdx.x*4 + (threadIdx.x >> 5);
    int lane = threadIdx.x & 31;
    int r = w & 63;
    float scale = g1[r] * rsqrtf(v1[r] + EPSC);
    float shift = b1[r] - m1[r]*scale;
    const float* row = g_tp + (size_t)w*HWs;
    float best = -3.4e38f; int bi = 0;
    #pragma unroll
    for (int i=0;i<25;i++){
        int idx = i*32 + lane;
        if (idx < HWs){
            float v = row[idx]*scale + shift;
            if (v > best){ best = v; bi = idx; }
        }
    }
    #pragma unroll
    for (int off=16; off; off>>=1){
        float ov = __shfl_down_sync(0xffffffffu, best, off);
        int oi = __shfl_down_sync(0xffffffffu, bi, off);
        if (ov > best || (ov == best && oi < bi)){ best = ov; bi = oi; }
    }
    if (lane == 0) g_spt[w] = bi;
}

// ---------------- 2: template_resample gather -> bf16 split [b][r][c]
__global__ void k_tresT(const float* __restrict__ x){
    int o = blockIdx.x*256 + threadIdx.x;
    int c = o & 511; int r = (o>>9) & 63; int b = o >> 15;
    int idx = g_spt[b*RR + r];
    float v = x[(size_t)(b*CC + c)*THW + idx];
    __nv_bfloat16 h, l; split_bf(v, h, l);
    g_trAh[o] = h; g_trAl[o] = l;
}

// ================= HMMA affinity: M=64, N=6272, K=512, 3-pass bf16 =========
#define ROWB   80
#define AF_STAGE (384*ROWB)       // 30720
#define AFF_SMEM (2*AF_STAGE)     // 61440

__global__ void __launch_bounds__(128, 3) k_affinity(){
    extern __shared__ char smem[];
    const uint32_t sb0 = smem_u32(smem);
    const int tid = threadIdx.x;
    const int wid = tid >> 5, lane = tid & 31;

    const int n0 = blockIdx.x * 128;
    const int b  = blockIdx.y;

    const __nv_bfloat16* Ah = g_trAh + (size_t)b*RR*512;
    const __nv_bfloat16* Al = g_trAl + (size_t)b*RR*512;
    const __nv_bfloat16* Bh = g_B1h + ((size_t)b*THW + n0)*512;
    const __nv_bfloat16* Bl = g_B1l + ((size_t)b*THW + n0)*512;

    float acc[4][4][4];
    #pragma unroll
    for (int i=0;i<4;i++)
        #pragma unroll
        for (int j=0;j<4;j++)
            #pragma unroll
            for (int q=0;q<4;q++) acc[i][j][q]=0.f;

    const int lrow = (lane & 7) + ((lane >> 3) & 1) * 8;
    const int lcol = (lane >> 4) * 16;

    auto load_chunk = [&](int i, int buf){
        uint32_t sbase = sb0 + buf*AF_STAGE;
        #pragma unroll
        for (int it=0; it<12; it++){
            int id = tid + it*128;           // 0..1535
            int row = id >> 2, c = id & 3;
            const __nv_bfloat16* g;
            if (row < 128) g = (row < 64 ? Ah : Al) + (size_t)(row & 63)*512;
            else           g = (row < 256 ? Bh : Bl) + (size_t)((row - 128) & 127)*512;
            cpa16(sbase + row*ROWB + c*16, g + i*32 + c*8);
        }
        CP_COMMIT();
    };

    load_chunk(0, 0);

    for (int i = 0; i < 16; i++){
        if (i < 15){ load_chunk(i+1, (i+1)&1); CP_WAIT(1); }
        else       { CP_WAIT(0); }
        __syncthreads();

        const uint32_t sbuf = sb0 + (i&1)*AF_STAGE;
        #pragma unroll
        for (int kt=0; kt<2; kt++){
            const uint32_t koff = kt*32 + lcol;
            uint32_t a[4][4], bh[2][4], bl[2][4];
            #pragma unroll
            for (int mt=0; mt<4; mt++)
                ldmx4(a[mt], sbuf + (uint32_t)(mt*16 + lrow)*ROWB + koff);
            #pragma unroll
            for (int np=0; np<2; np++)
                ldmx4(bh[np], sbuf + 128*ROWB + (uint32_t)(wid*32 + np*16 + lrow)*ROWB + koff);
            #pragma unroll
            for (int mt=0; mt<4; mt++)
                #pragma unroll
                for (int nt=0; nt<4; nt++)
                    mma16816(acc[mt][nt], a[mt],
                             (nt&1)?bh[nt>>1][1]:bh[nt>>1][0],
                             (nt&1)?bh[nt>>1][3]:bh[nt>>1][2]);
            #pragma unroll
            for (int np=0; np<2; np++)
                ldmx4(bl[np], sbuf + 256*ROWB + (uint32_t)(wid*32 + np*16 + lrow)*ROWB + koff);
            #pragma unroll
            for (int mt=0; mt<4; mt++)
                #pragma unroll
                for (int nt=0; nt<4; nt++)
                    mma16816(acc[mt][nt], a[mt],
                             (nt&1)?bl[nt>>1][1]:bl[nt>>1][0],
                             (nt&1)?bl[nt>>1][3]:bl[nt>>1][2]);
            #pragma unroll
            for (int mt=0; mt<4; mt++)
                ldmx4(a[mt], sbuf + 64*ROWB + (uint32_t)(mt*16 + lrow)*ROWB + koff);
            #pragma unroll
            for (int mt=0; mt<4; mt++)
                #pragma unroll
                for (int nt=0; nt<4; nt++)
                    mma16816(acc[mt][nt], a[mt],
                             (nt&1)?bh[nt>>1][1]:bh[nt>>1][0],
                             (nt&1)?bh[nt>>1][3]:bh[nt>>1][2]);
        }
        __syncthreads();
    }

    const int g = lane >> 2, t = lane & 3;
    float* OutB = g_aff + (size_t)b*RR*THW;
    #pragma unroll
    for (int mt=0; mt<4; mt++){
        #pragma unroll
        for (int nt=0; nt<4; nt++){
            int row0 = mt*16 + g;
            int col  = n0 + wid*32 + nt*8 + t*2;
            size_t o0 = (size_t)row0*THW + col;
            size_t o1 = o0 + (size_t)8*THW;
            *(float2*)&OutB[o0] = make_float2(acc[mt][nt][0], acc[mt][nt][1]);
            *(float2*)&OutB[o1] = make_float2(acc[mt][nt][2], acc[mt][nt][3]);
        }
    }
}

// ---------------- 4: top-4 over HW per (b,r,t)
__global__ void k_topk(){
    int w = blockIdx.x*4 + (threadIdx.x >> 5);
    int lane = threadIdx.x & 31;
    const float* row = g_aff + (size_t)(w >> 3)*THW + (w & 7)*HWs;
    float lv[25];
    #pragma unroll
    for (int i=0;i<25;i++){
        int idx = i*32 + lane;
        lv[i] = (idx < HWs) ? row[idx] : -3.4e38f;
    }
    for (int kq=0;kq<KK;kq++){
        float v = -3.4e38f; int pos = 0;
        #pragma unroll
        for (int i=0;i<25;i++) if (lv[i] > v){ v = lv[i]; pos = i; }
        int gi = pos*32 + lane;
        #pragma unroll
        for (int off=16; off; off>>=1){
            float ov = __shfl_down_sync(0xffffffffu, v, off);
            int oi = __shfl_down_sync(0xffffffffu, gi, off);
            if (ov > v || (ov == v && oi < gi)){ v = ov; gi = oi; }
        }
        gi = __shfl_sync(0xffffffffu, gi, 0);
        #pragma unroll
        for (int i=0;i<25;i++) if (i*32 + lane == gi) lv[i] = -3.4e38f;
        if (lane == 0) g_topk[w*KK + kq] = gi;
    }
}

// ---------------- 5: trajectory gather
__global__ void k_traj(const float* __restrict__ x){
    int o = blockIdx.x*256 + threadIdx.x;
    int r = o & 63, t = (o>>6)&7, c = (o>>9)&511, kq = (o>>18)&3, b = o>>20;
    int idx = g_topk[((b*RR + r)*TT + t)*KK + kq];
    g_traj[o] = x[((size_t)(b*CC + c)*TT + t)*HWs + idx];
}

// ---------------- 6: per-k projection
__global__ void __launch_bounds__(256) k_fusek(
    const float* __restrict__ wp,
    const float* __restrict__ g2, const float* __restrict__ b2,
    const float* __restrict__ m2, const float* __restrict__ v2)
{
    int blk = blockIdx.x;
    int b = blk >> 5, ks = (blk >> 3) & 3, t = blk & 7;
    int tid = threadIdx.x, tx = tid & 15, ty = tid >> 4;
    __shared__ float As[32][132];
    __shared__ float Bs[32][64];
    float acc[8][4];
    #pragma unroll
    for (int i=0;i<8;i++){
        #pragma unroll
        for (int j=0;j<4;j++) acc[i][j]=0.f;
    }
    const float* Tb = g_traj + (size_t)(b*KK + ks)*CC*(TT*RR) + t*RR;
    for (int cc = 0; cc < CC; cc += 32){
        #pragma unroll
        for (int i=0;i<16;i++){
            int l = tid + 256*i;
            int k = l & 31, m = l >> 5;
            As[k][m] = wp[m*514 + cc + k];
        }
        #pragma unroll
        for (int i=0;i<8;i++){
            int l = tid + 256*i;
            int n = l & 63, k = l >> 6;
            Bs[k][n] = Tb[(size_t)(cc + k)*(TT*RR) + n];
        }
        __syncthreads();
        #pragma unroll
        for (int k=0;k<32;k++){
            float4 a0 = *(const float4*)&As[k][ty*4];
            float4 a1 = *(const float4*)&As[k][64 + ty*4];
            float4 bv = *(const float4*)&Bs[k][tx*4];
            float av[8] = {a0.x,a0.y,a0.z,a0.w,a1.x,a1.y,a1.z,a1.w};
            float bw[4] = {bv.x,bv.y,bv.z,bv.w};
            #pragma unroll
            for (int i=0;i<8;i++){
                #pragma unroll
                for (int j=0;j<4;j++) acc[i][j] += av[i]*bw[j];
            }
        }
        __syncthreads();
    }
    #pragma unroll
    for (int j=0;j<4;j++){
        int r = tx*4 + j;
        int idx = g_topk[((b*RR + r)*TT + t)*KK + ks];
        float rv = (float)(idx / WW) * (1.f/28.f);
        float cv = (float)(idx % WW) * (1.f/28.f);
        #pragma unroll
        for (int i=0;i<8;i++){
            int q = (i<4) ? ty*4+i : 64 + ty*4 + i - 4;
            acc[i][j] += wp[q*514 + 512]*rv + wp[q*514 + 513]*cv;
        }
    }
    #pragma unroll
    for (int i=0;i<8;i++){
        int q = (i<4) ? ty*4+i : 64 + ty*4 + i - 4;
        float sc = g2[q]*rsqrtf(v2[q]+EPSC);
        float sh = b2[q] - m2[q]*sc;
        #pragma unroll
        for (int j=0;j<4;j++){
            int r = tx*4+j;
            g_fusek[((size_t)(b*KK+ks)*CQ + q)*(TT*RR) + t*RR + r] = acc[i][j]*sc + sh;
        }
    }
}

// ---------------- 7: max over k
__global__ void k_maxk(){
    int o = blockIdx.x*256 + threadIdx.x;
    int b = o >> 16, rem = o & 65535;
    float m = g_fusek[(size_t)(b*KK)*65536 + rem];
    #pragma unroll
    for (int ks=1; ks<KK; ks++)
        m = fmaxf(m, g_fusek[(size_t)(b*KK+ks)*65536 + rem]);
    g_fuse[o] = m;
}

// ---------------- 8: temporal conv + bn3 + relu -> A2 bf16 split
__global__ void __launch_bounds__(256) k_tconv(
    const float* __restrict__ wt,
    const float* __restrict__ g3, const float* __restrict__ b3,
    const float* __restrict__ m3, const float* __restrict__ v3)
{
    int b = blockIdx.x >> 3, t = blockIdx.x & 7;
    int coBase = blockIdx.y * 16;
    int r = threadIdx.x & 63;
    int g = threadIdx.x >> 6;
    float acc[4] = {0.f,0.f,0.f,0.f};
    const float* fbase = g_fuse + (size_t)b*CQ*(TT*RR);
    for (int ci=0; ci<CQ; ci++){
        #pragma unroll
        for (int j=0;j<3;j++){
            int tt = t + j - 1;
            if (tt < 0 || tt >= TT) continue;
            float f = fbase[ci*(TT*RR) + tt*RR + r];
            #pragma unroll
            for (int cc=0; cc<4; cc++){
                int co = coBase + g*4 + cc;
                acc[cc] += wt[(co*CQ + ci)*3 + j] * f;
            }
        }
    }
    #pragma unroll
    for (int cc=0; cc<4; cc++){
        int co = coBase + g*4 + cc;
        float sc = g3[co]*rsqrtf(v3[co]+EPSC);
        float sh = b3[co] - m3[co]*sc;
        float v = fmaxf(acc[cc]*sc + sh, 0.f);
        size_t o = (size_t)(b*CC + co)*(TT*RR) + t*RR + r;
        __nv_bfloat16 h, l; split_bf(v, h, l);
        g_A2h[o] = h; g_A2l[o] = l;
    }
}

// ---------------- 9: points (mean over k of traj) transposed + bf16 split
__global__ void __launch_bounds__(256) k_pointsT(){
    __shared__ float s[32][33];
    int ct = blockIdx.x, pt = blockIdx.y, b = blockIdx.z;
    int t = threadIdx.x;
    int rr = t >> 5, cl = t & 31;
    #pragma unroll
    for (int it=0; it<4; it++){
        int c = ct*32 + it*8 + rr;
        size_t base = ((size_t)c << 9) + pt*32 + cl;
        float sm = 0.f;
        #pragma unroll
        for (int k=0;k<KK;k++) sm += g_traj[(((size_t)(b*KK+k))<<18) + base];
        s[it*8+rr][cl] = sm * 0.25f;
    }
    __syncthreads();
    #pragma unroll
    for (int it=0; it<4; it++){
        int pl = it*8 + rr;
        float v = s[cl][pl];
        size_t o = ((size_t)(b*PP) + pt*32 + pl)*CC + ct*32 + cl;
        __nv_bfloat16 h, l; split_bf(v, h, l);
        g_A1h[o] = h; g_A1l[o] = l;
    }
}

// ---------------- 10: x transpose + split: B1[b][s][c] = x[b][c][s]
__global__ void __launch_bounds__(256) k_xT(const float* __restrict__ x){
    __shared__ float s[32][33];
    int ct = blockIdx.x, st = blockIdx.y, b = blockIdx.z;
    int t = threadIdx.x;
    int rr = t >> 5, cl = t & 31;
    #pragma unroll
    for (int it=0; it<4; it++){
        int c = ct*32 + it*8 + rr;
        s[it*8+rr][cl] = x[((size_t)(b*CC) + c)*THW + st*32 + cl];
    }
    __syncthreads();
    #pragma unroll
    for (int it=0; it<2; it++){
        int id = t + it*256;
        int sl = id >> 4;
        int cp = id & 15;
        float v0 = s[cp*2][sl];
        float v1 = s[cp*2+1][sl];
        __nv_bfloat16 h0,l0,h1,l1;
        split_bf(v0, h0, l0); split_bf(v1, h1, l1);
        size_t o = ((size_t)b*THW + st*32 + sl)*CC + ct*32 + cp*2;
        *(uint32_t*)&g_B1h[o] = pack_bf16(h0, h1);
        *(uint32_t*)&g_B1l[o] = pack_bf16(l0, l1);
    }
}

// ---------------- 11: row softmax on projT [s][p] -> B2 bf16 + sinv
__global__ void __launch_bounds__(256) k_soft(int wofs){
    int w = wofs + blockIdx.x*8 + (threadIdx.x >> 5);
    int lane = threadIdx.x & 31;
    const float* pr = g_proj + (size_t)w*PP;
    float v[16];
    #pragma unroll
    for (int j=0;j<4;j++){
        float4 t = *(const float4*)&pr[j*128 + lane*4];
        v[j*4+0]=t.x; v[j*4+1]=t.y; v[j*4+2]=t.z; v[j*4+3]=t.w;
    }
    float mx = v[0];
    #pragma unroll
    for (int i=1;i<16;i++) mx = fmaxf(mx, v[i]);
    #pragma unroll
    for (int off=16; off; off>>=1) mx = fmaxf(mx, __shfl_xor_sync(0xffffffffu, mx, off));
    float sm = 0.f;
    #pragma unroll
    for (int i=0;i<16;i++){ v[i] = __expf(v[i] - mx); sm += v[i]; }
    #pragma unroll
    for (int off=16; off; off>>=1) sm += __shfl_xor_sync(0xffffffffu, sm, off);
    if (lane == 0) g_sinv[w] = 1.f / sm;

    #pragma unroll
    for (int j=0;j<4;j++){
        __nv_bfloat16 h0 = __float2bfloat16(v[j*4+0]);
        __nv_bfloat16 h1 = __float2bfloat16(v[j*4+1]);
        __nv_bfloat16 h2 = __float2bfloat16(v[j*4+2]);
        __nv_bfloat16 h3 = __float2bfloat16(v[j*4+3]);
        size_t o = (size_t)w*PP + j*128 + lane*4;
        *(uint2*)&g_B2h[o] = make_uint2(pack_bf16(h0, h1), pack_bf16(h2, h3));
    }
}

// ================= HMMA GEMM 128x128, 256 thr ==============================
// MODE 0: projT[s][p] = xT @ pointsT^T   3-pass, 4 tiles (both splits)
// MODE 1: out = x + (tc @ expT^T)*sinv   2-pass, 3 tiles (A split, B single)
#define TILE_SM (128*ROWB)        // 10240
#define GSMEM0 (2*4*TILE_SM)      // 81920
#define GSMEM1 (2*3*TILE_SM)      // 61440

template<int MODE>
__global__ void __launch_bounds__(256, 2)
gemm_bf16(const float* __restrict__ X, float* __restrict__ Out, int bofs)
{
    constexpr int NT = (MODE==0) ? 4 : 3;
    constexpr int STAGE = NT*TILE_SM;

    extern __shared__ char smem[];
    const uint32_t sb0 = smem_u32(smem);
    const int tid = threadIdx.x;
    const int wid = tid >> 5, lane = tid & 31;
    const int warp_m = wid >> 2, warp_n = wid & 3;

    const int n0 = blockIdx.x * 128;
    const int m0 = blockIdx.y * 128;
    const int b  = blockIdx.z + bofs;

    const __nv_bfloat16* tp[NT];
    if (MODE == 0){
        tp[0] = g_B1h + ((size_t)b*THW + m0)*512;
        tp[1] = g_B1l + ((size_t)b*THW + m0)*512;
        tp[2] = g_A1h + ((size_t)(b*512) + n0)*512;
        tp[3] = g_A1l + ((size_t)(b*512) + n0)*512;
    } else {
        tp[0] = g_A2h + ((size_t)(b*512) + m0)*512;
        tp[1] = g_A2l + ((size_t)(b*512) + m0)*512;
        tp[2] = g_B2h + ((size_t)b*THW + n0)*512;
    }

    float acc[4][4][4];
    #pragma unroll
    for (int i=0;i<4;i++)
        #pragma unroll
        for (int j=0;j<4;j++)
            #pragma unroll
            for (int q=0;q<4;q++) acc[i][j][q]=0.f;

    const int lrow = (lane & 7) + ((lane >> 3) & 1) * 8;
    const int lcol = (lane >> 4) * 16;

    auto load_chunk = [&](int i, int buf){
        uint32_t sbase = sb0 + buf*STAGE;
        #pragma unroll
        for (int it=0; it<2*NT; it++){
            int id = tid + it*256;
            int row = id >> 2, c = id & 3;
            int tile = row >> 7, rowin = row & 127;
            const __nv_bfloat16* g = tp[tile] + (size_t)rowin*512 + i*32 + c*8;
            cpa16(sbase + tile*TILE_SM + rowin*ROWB + c*16, g);
        }
        CP_COMMIT();
    };

    load_chunk(0, 0);

    for (int i = 0; i < 16; i++){
        if (i < 15){ load_chunk(i+1, (i+1)&1); CP_WAIT(1); }
        else       { CP_WAIT(0); }
        __syncthreads();

        const uint32_t sbuf = sb0 + (i&1)*STAGE;
        #pragma unroll
        for (int kt=0; kt<2; kt++){
            const uint32_t koff = kt*32 + lcol;
            uint32_t a[4][4], bh[2][4];
            const uint32_t arow = (uint32_t)(warp_m*64 + lrow)*ROWB + koff;
            const uint32_t brow = (uint32_t)(warp_n*32 + lrow)*ROWB + koff;

            if (MODE == 0){
                #pragma unroll
                for (int mt=0; mt<4; mt++)
                    ldmx4(a[mt], sbuf + arow + (uint32_t)(mt*16)*ROWB);
                #pragma unroll
                for (int np=0; np<2; np++)
                    ldmx4(bh[np], sbuf + 2*TILE_SM + brow + (uint32_t)(np*16)*ROWB);
                #pragma unroll
                for (int mt=0; mt<4; mt++)
                    #pragma unroll
                    for (int nt=0; nt<4; nt++)
                        mma16816(acc[mt][nt], a[mt],
                                 (nt&1)?bh[nt>>1][1]:bh[nt>>1][0],
                                 (nt&1)?bh[nt>>1][3]:bh[nt>>1][2]);
                {
                    uint32_t bl[2][4];
                    #pragma unroll
                    for (int np=0; np<2; np++)
                        ldmx4(bl[np], sbuf + 3*TILE_SM + brow + (uint32_t)(np*16)*ROWB);
                    #pragma unroll
                    for (int mt=0; mt<4; mt++)
                        #pragma unroll
                        for (int nt=0; nt<4; nt++)
                            mma16816(acc[mt][nt], a[mt],
                                     (nt&1)?bl[nt>>1][1]:bl[nt>>1][0],
                                     (nt&1)?bl[nt>>1][3]:bl[nt>>1][2]);
                }
                #pragma unroll
                for (int mt=0; mt<4; mt++)
                    ldmx4(a[mt], sbuf + TILE_SM + arow + (uint32_t)(mt*16)*ROWB);
                #pragma unroll
                for (int mt=0; mt<4; mt++)
                    #pragma unroll
                    for (int nt=0; nt<4; nt++)
                        mma16816(acc[mt][nt], a[mt],
                                 (nt&1)?bh[nt>>1][1]:bh[nt>>1][0],
                                 (nt&1)?bh[nt>>1][3]:bh[nt>>1][2]);
            } else {
                #pragma unroll
                for (int np=0; np<2; np++)
                    ldmx4(bh[np], sbuf + 2*TILE_SM + brow + (uint32_t)(np*16)*ROWB);
                #pragma unroll
                for (int p=0; p<2; p++){
                    #pragma unroll
                    for (int mt=0; mt<4; mt++)
                        ldmx4(a[mt], sbuf + p*TILE_SM + arow + (uint32_t)(mt*16)*ROWB);
                    #pragma unroll
                    for (int mt=0; mt<4; mt++)
                        #pragma unroll
                        for (int nt=0; nt<4; nt++)
                            mma16816(acc[mt][nt], a[mt],
                                     (nt&1)?bh[nt>>1][1]:bh[nt>>1][0],
                                     (nt&1)?bh[nt>>1][3]:bh[nt>>1][2]);
                }
            }
        }
        __syncthreads();
    }

    const size_t ostride = (MODE == 0) ? 512 : THW;
    float* OutB = (MODE==0 ? g_proj + (size_t)b*THW*512 : Out + (size_t)b*512*THW);
    const float* Xb = X + (size_t)b*512*THW;
    const float* sinvb = g_sinv + b*THW;
    const int g = lane >> 2, t = lane & 3;

    #pragma unroll
    for (int mt=0; mt<4; mt++){
        #pragma unroll
        for (int nt=0; nt<4; nt++){
            int row0 = m0 + warp_m*64 + mt*16 + g;
            int col  = n0 + warp_n*32 + nt*8 + t*2;
            size_t o0 = (size_t)row0*ostride + col;
            size_t o1 = o0 + 8*ostride;
            if (MODE == 0){
                *(float2*)&OutB[o0] = make_float2(acc[mt][nt][0], acc[mt][nt][1]);
                *(float2*)&OutB[o1] = make_float2(acc[mt][nt][2], acc[mt][nt][3]);
            } else {
                float2 sv = *(const float2*)&sinvb[col];
                float2 x0 = *(const float2*)&Xb[o0];
                float2 x1 = *(const float2*)&Xb[o1];
                *(float2*)&OutB[o0] = make_float2(fmaf(acc[mt][nt][0], sv.x, x0.x),
                                                  fmaf(acc[mt][nt][1], sv.y, x0.y));
                *(float2*)&OutB[o1] = make_float2(fmaf(acc[mt][nt][2], sv.x, x1.x),
                                                  fmaf(acc[mt][nt][3], sv.y, x1.y));
            }
        }
    }
}

// ---------------- launch (stream fork/join + batch-halved gemm pipeline) ----
extern "C" void kernel_launch(void* const* d_in, const int* in_sizes, int n_in,
                              void* d_out, int out_size)
{
    const float* x  = (const float*)d_in[0];
    const float* wr = (const float*)d_in[1];
    const float* g1 = (const float*)d_in[2];
    const float* b1 = (const float*)d_in[3];
    const float* m1 = (const float*)d_in[4];
    const float* v1 = (const float*)d_in[5];
    const float* wp = (const float*)d_in[6];
    const float* g2 = (const float*)d_in[7];
    const float* b2 = (const float*)d_in[8];
    const float* m2 = (const float*)d_in[9];
    const float* v2 = (const float*)d_in[10];
    const float* wt = (const float*)d_in[11];
    const float* g3 = (const float*)d_in[12];
    const float* b3 = (const float*)d_in[13];
    const float* m3 = (const float*)d_in[14];
    const float* v3 = (const float*)d_in[15];
    float* out = (float*)d_out;

    static cudaStream_t s1 = nullptr;
    static cudaEvent_t evF1, evJ1, evF2, evA, evT, evB;
    static int inited = 0;
    if (!inited){
        cudaStreamCreateWithFlags(&s1, cudaStreamNonBlocking);
        cudaEventCreateWithFlags(&evF1, cudaEventDisableTiming);
        cudaEventCreateWithFlags(&evJ1, cudaEventDisableTiming);
        cudaEventCreateWithFlags(&evF2, cudaEventDisableTiming);
        cudaEventCreateWithFlags(&evA,  cudaEventDisableTiming);
        cudaEventCreateWithFlags(&evT,  cudaEventDisableTiming);
        cudaEventCreateWithFlags(&evB,  cudaEventDisableTiming);
        cudaFuncSetAttribute(gemm_bf16<0>, cudaFuncAttributeMaxDynamicSharedMemorySize, GSMEM0);
        cudaFuncSetAttribute(gemm_bf16<1>, cudaFuncAttributeMaxDynamicSharedMemorySize, GSMEM1);
        cudaFuncSetAttribute(k_affinity, cudaFuncAttributeMaxDynamicSharedMemorySize, AFF_SMEM);
        inited = 1;
    }

    // ---- fork 1: template chain on s1, xT on main ----
    cudaEventRecord(evF1, 0);
    cudaStreamWaitEvent(s1, evF1, 0);
    k_tp<<<dim3(7, BB), 256, 0, s1>>>(x, wr);
    k_tp_argmax<<<BB*RR/4, 128, 0, s1>>>(g1, b1, m1, v1);
    k_tresT<<<(BB*RR*CC)/256, 256, 0, s1>>>(x);
    cudaEventRecord(evJ1, s1);

    k_xT<<<dim3(16, 196, BB), 256>>>(x);
    cudaStreamWaitEvent(0, evJ1, 0);

    // ---- serial: affinity -> topk -> traj ----
    k_affinity<<<dim3(49, BB), 128, AFF_SMEM>>>();
    k_topk<<<(BB*RR*TT)/4, 128>>>();
    k_traj<<<(BB*KK*CC*TT*RR)/256, 256>>>(x);

    // ---- fork 2: fusek->maxk->tconv on s1 ----
    cudaEventRecord(evF2, 0);
    cudaStreamWaitEvent(s1, evF2, 0);
    k_fusek<<<BB*KK*TT, 256, 0, s1>>>(wp, g2, b2, m2, v2);
    k_maxk<<<(BB*CQ*TT*RR)/256, 256, 0, s1>>>();
    k_tconv<<<dim3(BB*TT, CC/16), 256, 0, s1>>>(wt, g3, b3, m3, v3);
    cudaEventRecord(evT, s1);

    // ---- main: pointsT -> gemm0 halves ----
    k_pointsT<<<dim3(16, 16, BB), 256>>>();
    gemm_bf16<0><<<dim3(4, 49, 4), 256, GSMEM0>>>(nullptr, nullptr, 0);
    cudaEventRecord(evA, 0);
    gemm_bf16<0><<<dim3(4, 49, 4), 256, GSMEM0>>>(nullptr, nullptr, 4);

    // ---- s1: soft + gemm1 for batches 0-3 (after gemm0_h0 & its own tconv) ----
    cudaStreamWaitEvent(s1, evA, 0);
    k_soft<<<(4*THW)/8, 256, 0, s1>>>(0);
    gemm_bf16<1><<<dim3(49, 4, 4), 256, GSMEM1, s1>>>(x, out, 0);
    cudaEventRecord(evB, s1);

    // ---- main: soft + gemm1 for batches 4-7 ----
    k_soft<<<(4*THW)/8, 256>>>(4*THW);
    cudaStreamWaitEvent(0, evT, 0);
    gemm_bf16<1><<<dim3(49, 4, 4), 256, GSMEM1>>>(x, out, 4);
    cudaStreamWaitEvent(0, evB, 0);
}